// round 11
// baseline (speedup 1.0000x reference)
#include <cuda_runtime.h>
#include <cuda_fp16.h>
#include <cstdint>
#include <math.h>

#define BSZ  4096
#define OUTF 2048
#define NG   8192
#define KDIM 2048

// o-gate pre-activations scratch [B, OUT] (compact, fp32)
__device__ float g_gates[(size_t)BSZ * OUTF];   // 32 MiB

// fp16 copies (filled by prologue converts / gates epilogue)
__device__ __half g_xh [(size_t)BSZ * KDIM];
__device__ __half g_hxh[(size_t)BSZ * KDIM];
__device__ __half g_cxh[(size_t)BSZ * KDIM];
__device__ __half g_cyh[(size_t)BSZ * KDIM];
__device__ __half g_wih[(size_t)NG * KDIM];
__device__ __half g_whh[(size_t)NG * KDIM];
__device__ __half g_wp [(size_t)2 * OUTF * KDIM];   // w_pi rows then w_pf rows
__device__ __half g_wpo[(size_t)OUTF * KDIM];
__device__ __half g_zero[(size_t)32 * KDIM];        // static zeros (peephole filler)

__device__ __forceinline__ uint32_t smem_u32(const void* p) {
    uint32_t a;
    asm("{ .reg .u64 t; cvta.to.shared.u64 t, %1; cvt.u32.u64 %0, t; }" : "=r"(a) : "l"(p));
    return a;
}
__device__ __forceinline__ float sigf(float x) { return 1.0f / (1.0f + expf(-x)); }

__device__ __forceinline__ uint32_t sw128(uint32_t off) {
    return off ^ ((off >> 3) & 0x70);
}

__device__ __forceinline__ void ldsm4(uint32_t addr, uint32_t* r) {
    asm volatile("ldmatrix.sync.aligned.m8n8.x4.shared.b16 {%0,%1,%2,%3}, [%4];"
        : "=r"(r[0]), "=r"(r[1]), "=r"(r[2]), "=r"(r[3]) : "r"(addr));
}

__device__ __forceinline__ void mma16816(float* d, const uint32_t* a, const uint32_t* b) {
    asm volatile(
        "mma.sync.aligned.m16n8k16.row.col.f32.f16.f16.f32 "
        "{%0,%1,%2,%3}, {%4,%5,%6,%7}, {%8,%9}, {%0,%1,%2,%3};"
        : "+f"(d[0]), "+f"(d[1]), "+f"(d[2]), "+f"(d[3])
        : "r"(a[0]), "r"(a[1]), "r"(a[2]), "r"(a[3]), "r"(b[0]), "r"(b[1]));
}

__device__ __forceinline__ void cpa16(uint32_t dst, const void* src) {
    asm volatile("cp.async.cg.shared.global [%0], [%1], 16;" :: "r"(dst), "l"(src));
}
#define CP_COMMIT() asm volatile("cp.async.commit_group;" ::: "memory")
#define CP_WAIT1()  asm volatile("cp.async.wait_group 1;"  ::: "memory")
#define CP_WAIT0()  asm volatile("cp.async.wait_group 0;"  ::: "memory")

// ---------------- SMEM layout ----------------
// header 1024B: bias[128] floats (gate-major) for the gates kernel
// stage (32KB): A 16KB (128 rows x 128B) | B 16KB (128 rows x 128B), fp16, SW128
// 3 stages; ~97KB/CTA -> 2 CTAs per SM. Epilogue exchange buffer overlays stages.
#define HDR       1024
#define T_A       0
#define T_B       16384
#define STAGE_SZ  32768
#define NSTAGE    3
#define SMEM_TOTAL (HDR + NSTAGE * STAGE_SZ)   // 99328
#define EX_STRIDE 132                           // floats; 128x132x4B = 67.6KB <= 96KB

// async-load one K=64 chunk, single-B-region variant (gemm_out).
__device__ __forceinline__ void load_chunk1(const __half* __restrict__ Ab,
                                            const __half* __restrict__ Bb,
                                            uint32_t stage, int tid) {
    #pragma unroll
    for (int it = 0; it < 4; ++it) {
        int idx = tid + it * 256;
        int r = idx >> 3, c16 = idx & 7;
        cpa16(stage + T_A + sw128((uint32_t)(r * 128 + c16 * 16)),
              Ab + (size_t)r * KDIM + c16 * 8);
    }
    #pragma unroll
    for (int it = 0; it < 4; ++it) {
        int idx = tid + it * 256;
        int r = idx >> 3, c16 = idx & 7;
        cpa16(stage + T_B + sw128((uint32_t)(r * 128 + c16 * 16)),
              Bb + (size_t)r * KDIM + c16 * 8);
    }
}

// async-load one K=64 chunk, 4-gate B gather (gates kernel).
// B tile rows: r in [0,128); gate g = r>>5 selects base, local row = r&31.
__device__ __forceinline__ void load_chunk4(const __half* __restrict__ Ab,
                                            const __half* __restrict__ B0,
                                            const __half* __restrict__ B1,
                                            const __half* __restrict__ B2,
                                            const __half* __restrict__ B3,
                                            uint32_t stage, int tid) {
    #pragma unroll
    for (int it = 0; it < 4; ++it) {
        int idx = tid + it * 256;
        int r = idx >> 3, c16 = idx & 7;
        cpa16(stage + T_A + sw128((uint32_t)(r * 128 + c16 * 16)),
              Ab + (size_t)r * KDIM + c16 * 8);
    }
    #pragma unroll
    for (int it = 0; it < 4; ++it) {
        int idx = tid + it * 256;
        int r = idx >> 3, c16 = idx & 7;
        int g = r >> 5, lr = r & 31;
        const __half* base = (g & 2) ? ((g & 1) ? B3 : B2)
                                     : ((g & 1) ? B1 : B0);
        cpa16(stage + T_B + sw128((uint32_t)(r * 128 + c16 * 16)),
              base + (size_t)lr * KDIM + c16 * 8);
    }
}

// Compute one K=64 chunk (4 k16 steps): warp tile 64(M) x 32(N).
__device__ __forceinline__ void compute_chunk(uint32_t stage_addr, int wm, int wn,
                                              int lane, float (&acc)[4][4][4]) {
    const uint32_t a_base = stage_addr + T_A;
    const uint32_t b_base = stage_addr + T_B;
    const int a_m = lane % 16;
    const int a_k = (lane / 16) * 8;
    const int b_n = (lane / 16) * 8 + (lane % 8);
    const int b_k = ((lane / 8) % 2) * 8;

    #pragma unroll
    for (int kk = 0; kk < 4; ++kk) {
        uint32_t Ah[4][4], Bh[2][4];
        #pragma unroll
        for (int mt = 0; mt < 4; ++mt) {
            uint32_t off = sw128((uint32_t)((wm + mt * 16 + a_m) * 128 + kk * 32 + a_k * 2));
            ldsm4(a_base + off, Ah[mt]);
        }
        #pragma unroll
        for (int nt = 0; nt < 2; ++nt) {
            uint32_t off = sw128((uint32_t)((wn + nt * 16 + b_n) * 128 + kk * 32 + b_k * 2));
            ldsm4(b_base + off, Bh[nt]);
        }
        #pragma unroll
        for (int mt = 0; mt < 4; ++mt)
            #pragma unroll
            for (int n8 = 0; n8 < 4; ++n8)
                mma16816(acc[mt][n8], Ah[mt], &Bh[n8 >> 1][(n8 & 1) * 2]);
    }
}

// ---------------------------------------------------------------------------
// Merged fp32 -> fp16 converter: grid.y selects segment, grid-stride in x.
// ---------------------------------------------------------------------------
struct F2HSeg { const float4* src; uint2* dst; int n4; };

__global__ __launch_bounds__(256)
void f2h_all(F2HSeg s0, F2HSeg s1, F2HSeg s2, F2HSeg s3,
             F2HSeg s4, F2HSeg s5, F2HSeg s6, F2HSeg s7) {
    F2HSeg s;
    switch (blockIdx.y) {
        case 0: s = s0; break; case 1: s = s1; break;
        case 2: s = s2; break; case 3: s = s3; break;
        case 4: s = s4; break; case 5: s = s5; break;
        case 6: s = s6; break; default: s = s7; break;
    }
    const int stride = gridDim.x * blockDim.x;
    for (int i = blockIdx.x * blockDim.x + threadIdx.x; i < s.n4; i += stride) {
        float4 v = s.src[i];
        __half2 h0 = __floats2half2_rn(v.x, v.y);
        __half2 h1 = __floats2half2_rn(v.z, v.w);
        s.dst[i] = make_uint2(*reinterpret_cast<uint32_t*>(&h0),
                              *reinterpret_cast<uint32_t*>(&h1));
    }
}

// ---------------------------------------------------------------------------
// GEMM1 + cell fused. Each CTA: 128 batch rows x 32 output cols x ALL 4 gates.
// B tile (128 rows) gathers 32 rows from each gate block. After the GEMM,
// i/f/g/o live in-CTA -> smem exchange -> cell update -> write cy (fp32+fp16)
// and o-gate preactivation.
// grid = (32 m-tiles, 64 col-tiles), block = 256, 2 CTAs/SM.
// ---------------------------------------------------------------------------
__global__ __launch_bounds__(256, 2)
void gemm_gates_cell(const float* __restrict__ b_ih, const float* __restrict__ b_hh,
                     const float* __restrict__ cx,
                     const float* __restrict__ td0, const float* __restrict__ td1,
                     const float* __restrict__ aS,  const float* __restrict__ bS,
                     float* __restrict__ cy_out)
{
    extern __shared__ char sm[];
    const int tid  = threadIdx.x;
    const int wid  = tid >> 5;
    const int lane = tid & 31;
    const int m0   = blockIdx.x * 128;
    const int n0   = blockIdx.y * 32;          // column block within OUTF
    const int wm   = (wid & 1) * 64;
    const int wn   = (wid >> 1) * 32;          // gate-major column in [0,128)

    // bias, gate-major: bsum[g*32 + j] = b_ih[g*OUTF+n0+j] + b_hh[...]
    float* bsum = reinterpret_cast<float*>(sm);
    if (tid < 128) {
        int g = tid >> 5, j = tid & 31;
        bsum[tid] = b_ih[g * OUTF + n0 + j] + b_hh[g * OUTF + n0 + j];
    }

    const uint32_t smb = smem_u32(sm);
    const __half* segA[3];
    segA[0] = g_xh  + (size_t)m0 * KDIM;
    segA[1] = g_hxh + (size_t)m0 * KDIM;
    segA[2] = g_cxh + (size_t)m0 * KDIM;
    // B bases per segment per gate
    const __half* segB[3][4];
    #pragma unroll
    for (int g = 0; g < 4; ++g) {
        segB[0][g] = g_wih + (size_t)(g * OUTF + n0) * KDIM;
        segB[1][g] = g_whh + (size_t)(g * OUTF + n0) * KDIM;
    }
    segB[2][0] = g_wp + (size_t)n0 * KDIM;            // w_pi rows (i gate)
    segB[2][1] = g_wp + (size_t)(OUTF + n0) * KDIM;   // w_pf rows (f gate)
    segB[2][2] = g_zero;                              // g gate: no peephole
    segB[2][3] = g_zero;                              // o gate: no peephole

    float acc[4][4][4];
    #pragma unroll
    for (int i = 0; i < 4; ++i)
        #pragma unroll
        for (int j = 0; j < 4; ++j)
            #pragma unroll
            for (int k = 0; k < 4; ++k) acc[i][j][k] = 0.f;

    const int nch = 3 * 32;

    auto issue = [&](int c) {
        const int seg = c >> 5;
        const int kc  = (c & 31) << 6;
        load_chunk4(segA[seg] + kc,
                    segB[seg][0] + kc, segB[seg][1] + kc,
                    segB[seg][2] + kc, segB[seg][3] + kc,
                    smb + HDR + (uint32_t)(c % NSTAGE) * STAGE_SZ, tid);
        CP_COMMIT();
    };

    issue(0);
    issue(1);

    for (int c = 0; c < nch; ++c) {
        if (c + 1 < nch) { CP_WAIT1(); } else { CP_WAIT0(); }
        __syncthreads();
        if (c + 2 < nch) issue(c + 2);
        compute_chunk(smb + HDR + (uint32_t)(c % NSTAGE) * STAGE_SZ, wm, wn, lane, acc);
    }

    // ---- epilogue: exchange through smem, then fused cell update ----
    __syncthreads();   // all compute done; stages reusable as exchange buffer
    float* ex = reinterpret_cast<float*>(sm + HDR);   // [128 rows][EX_STRIDE]

    #pragma unroll
    for (int mt = 0; mt < 4; ++mt) {
        #pragma unroll
        for (int n8 = 0; n8 < 4; ++n8) {
            int bcol = wn + n8 * 8 + (lane % 4) * 2;
            float bx0 = bsum[bcol], bx1 = bsum[bcol + 1];
            int r0 = wm + mt * 16 + lane / 4;
            *reinterpret_cast<float2*>(ex + (size_t)r0 * EX_STRIDE + bcol) =
                make_float2(acc[mt][n8][0] + bx0, acc[mt][n8][1] + bx1);
            *reinterpret_cast<float2*>(ex + (size_t)(r0 + 8) * EX_STRIDE + bcol) =
                make_float2(acc[mt][n8][2] + bx0, acc[mt][n8][3] + bx1);
        }
    }
    __syncthreads();

    // cell: 128 rows x 32 cols; 2 threads per row, 16 cols each (4x float4)
    {
        const int row = tid >> 1;
        const int c0  = (tid & 1) * 16;
        const int gr  = m0 + row;
        const float aa = aS[0], bb = bS[0];
        const float forc = aa * expf(-bb * td0[gr]);
        const float inc  = aa * expf(-bb * td1[gr]);
        const float* exr = ex + (size_t)row * EX_STRIDE;

        #pragma unroll
        for (int j4 = 0; j4 < 4; ++j4) {
            int j = c0 + j4 * 4;
            float4 iv = *reinterpret_cast<const float4*>(exr + j);
            float4 fv = *reinterpret_cast<const float4*>(exr + 32 + j);
            float4 gv = *reinterpret_cast<const float4*>(exr + 64 + j);
            float4 ov = *reinterpret_cast<const float4*>(exr + 96 + j);
            float4 cxv = *reinterpret_cast<const float4*>(cx + (size_t)gr * OUTF + n0 + j);

            float4 cyv;
            cyv.x = forc * sigf(fv.x) * cxv.x + inc * sigf(iv.x) * tanhf(gv.x);
            cyv.y = forc * sigf(fv.y) * cxv.y + inc * sigf(iv.y) * tanhf(gv.y);
            cyv.z = forc * sigf(fv.z) * cxv.z + inc * sigf(iv.z) * tanhf(gv.z);
            cyv.w = forc * sigf(fv.w) * cxv.w + inc * sigf(iv.w) * tanhf(gv.w);

            *reinterpret_cast<float4*>(cy_out + (size_t)gr * OUTF + n0 + j) = cyv;
            __half2 h0 = __floats2half2_rn(cyv.x, cyv.y);
            __half2 h1 = __floats2half2_rn(cyv.z, cyv.w);
            *reinterpret_cast<uint2*>(g_cyh + (size_t)gr * OUTF + n0 + j) =
                make_uint2(*reinterpret_cast<uint32_t*>(&h0),
                           *reinterpret_cast<uint32_t*>(&h1));
            *reinterpret_cast<float4*>(g_gates + (size_t)gr * OUTF + n0 + j) = ov;
        }
    }
}

// ---------------------------------------------------------------------------
// GEMM3: O = cy @ w_po^T ; hy = sigmoid(o_preact + O) * tanh(cy)
// grid = (32 m-tiles, 16 n-tiles), block = 256. CTA tile 128x128, 2 CTAs/SM.
// ---------------------------------------------------------------------------
__global__ __launch_bounds__(256, 2)
void gemm_out(const float* __restrict__ cy, float* __restrict__ hy)
{
    extern __shared__ char sm[];
    const int tid  = threadIdx.x;
    const int wid  = tid >> 5;
    const int lane = tid & 31;
    const int m0   = blockIdx.x * 128;
    const int n0   = blockIdx.y * 128;
    const int wm   = (wid & 1) * 64;
    const int wn   = (wid >> 1) * 32;

    const uint32_t smb = smem_u32(sm);
    const __half* Ab = g_cyh + (size_t)m0 * KDIM;
    const __half* Bb = g_wpo + (size_t)n0 * KDIM;

    float acc[4][4][4];
    #pragma unroll
    for (int i = 0; i < 4; ++i)
        #pragma unroll
        for (int j = 0; j < 4; ++j)
            #pragma unroll
            for (int k = 0; k < 4; ++k) acc[i][j][k] = 0.f;

    const int nch = 32;

    auto issue = [&](int c) {
        const int kc = c << 6;
        load_chunk1(Ab + kc, Bb + kc,
                    smb + HDR + (uint32_t)(c % NSTAGE) * STAGE_SZ, tid);
        CP_COMMIT();
    };

    issue(0);
    issue(1);

    for (int c = 0; c < nch; ++c) {
        if (c + 1 < nch) { CP_WAIT1(); } else { CP_WAIT0(); }
        __syncthreads();
        if (c + 2 < nch) issue(c + 2);
        compute_chunk(smb + HDR + (uint32_t)(c % NSTAGE) * STAGE_SZ, wm, wn, lane, acc);
    }

    // fused epilogue
    #pragma unroll
    for (int mt = 0; mt < 4; ++mt) {
        #pragma unroll
        for (int n8 = 0; n8 < 4; ++n8) {
            int col = n0 + wn + n8 * 8 + (lane % 4) * 2;
            #pragma unroll
            for (int half = 0; half < 2; ++half) {
                int row = m0 + wm + mt * 16 + lane / 4 + half * 8;
                const float* gorow = g_gates + (size_t)row * OUTF + col;
                const float* cyrow = cy + (size_t)row * OUTF + col;
                float*       hyrow = hy + (size_t)row * OUTF + col;
                float2 go  = *reinterpret_cast<const float2*>(gorow);
                float2 cyv = *reinterpret_cast<const float2*>(cyrow);
                float2 r;
                r.x = sigf(go.x + acc[mt][n8][half * 2 + 0]) * tanhf(cyv.x);
                r.y = sigf(go.y + acc[mt][n8][half * 2 + 1]) * tanhf(cyv.y);
                *reinterpret_cast<float2*>(hyrow) = r;
            }
        }
    }
}

// ---------------------------------------------------------------------------
extern "C" void kernel_launch(void* const* d_in, const int* in_sizes, int n_in,
                              void* d_out, int out_size)
{
    (void)in_sizes; (void)n_in; (void)out_size;
    const float* x    = (const float*)d_in[0];
    const float* td0  = (const float*)d_in[1];
    const float* td1  = (const float*)d_in[2];
    const float* hx   = (const float*)d_in[3];
    const float* cx   = (const float*)d_in[4];
    const float* w_ih = (const float*)d_in[5];
    const float* w_hh = (const float*)d_in[6];
    const float* w_pi = (const float*)d_in[7];
    const float* w_pf = (const float*)d_in[8];
    const float* w_po = (const float*)d_in[9];
    const float* b_ih = (const float*)d_in[10];
    const float* b_hh = (const float*)d_in[11];
    const float* aS   = (const float*)d_in[12];
    const float* bS   = (const float*)d_in[13];

    float* out = (float*)d_out;
    float* hy  = out;                        // [B, OUT]
    float* cy  = out + (size_t)BSZ * OUTF;   // [B, OUT]

    // symbol addresses for fp16 buffers
    void *p_xh, *p_hxh, *p_cxh, *p_wih, *p_whh, *p_wp, *p_wpo;
    cudaGetSymbolAddress(&p_xh,  g_xh);
    cudaGetSymbolAddress(&p_hxh, g_hxh);
    cudaGetSymbolAddress(&p_cxh, g_cxh);
    cudaGetSymbolAddress(&p_wih, g_wih);
    cudaGetSymbolAddress(&p_whh, g_whh);
    cudaGetSymbolAddress(&p_wp,  g_wp);
    cudaGetSymbolAddress(&p_wpo, g_wpo);

    const int actN4 = BSZ * KDIM / 4;        // activations
    const int wBigN4 = NG * KDIM / 4;        // w_ih / w_hh
    const int wSmN4 = OUTF * KDIM / 4;       // peephole / output weights

    F2HSeg s0 = {(const float4*)x,    (uint2*)p_xh,  actN4};
    F2HSeg s1 = {(const float4*)hx,   (uint2*)p_hxh, actN4};
    F2HSeg s2 = {(const float4*)cx,   (uint2*)p_cxh, actN4};
    F2HSeg s3 = {(const float4*)w_ih, (uint2*)p_wih, wBigN4};
    F2HSeg s4 = {(const float4*)w_hh, (uint2*)p_whh, wBigN4};
    F2HSeg s5 = {(const float4*)w_pi, (uint2*)p_wp,  wSmN4};
    F2HSeg s6 = {(const float4*)w_pf,
                 (uint2*)((char*)p_wp + (size_t)OUTF * KDIM * sizeof(__half)), wSmN4};
    F2HSeg s7 = {(const float4*)w_po, (uint2*)p_wpo, wSmN4};

    f2h_all<<<dim3(1024, 8), 256>>>(s0, s1, s2, s3, s4, s5, s6, s7);

    cudaFuncSetAttribute(gemm_gates_cell, cudaFuncAttributeMaxDynamicSharedMemorySize, SMEM_TOTAL);
    cudaFuncSetAttribute(gemm_out,        cudaFuncAttributeMaxDynamicSharedMemorySize, SMEM_TOTAL);

    gemm_gates_cell<<<dim3(BSZ / 128, OUTF / 32), 256, SMEM_TOTAL>>>(
        b_ih, b_hh, cx, td0, td1, aS, bS, cy);

    gemm_out<<<dim3(BSZ / 128, OUTF / 128), 256, SMEM_TOTAL>>>(cy, hy);
}

// round 12
// speedup vs baseline: 1.0223x; 1.0223x over previous
#include <cuda_runtime.h>
#include <cuda_fp16.h>
#include <cstdint>
#include <math.h>

#define BSZ  4096
#define OUTF 2048
#define NG   8192
#define KDIM 2048

// o-gate pre-activations scratch [B, OUT] (compact, fp32)
__device__ float g_gates[(size_t)BSZ * OUTF];   // 32 MiB

// fp16 copies (filled by prologue converts / gates epilogue)
__device__ __half g_xh [(size_t)BSZ * KDIM];
__device__ __half g_hxh[(size_t)BSZ * KDIM];
__device__ __half g_cxh[(size_t)BSZ * KDIM];
__device__ __half g_cyh[(size_t)BSZ * KDIM];
__device__ __half g_wih[(size_t)NG * KDIM];
__device__ __half g_whh[(size_t)NG * KDIM];
__device__ __half g_wp [(size_t)2 * OUTF * KDIM];   // w_pi rows then w_pf rows
__device__ __half g_wpo[(size_t)OUTF * KDIM];

__device__ __forceinline__ uint32_t smem_u32(const void* p) {
    uint32_t a;
    asm("{ .reg .u64 t; cvta.to.shared.u64 t, %1; cvt.u32.u64 %0, t; }" : "=r"(a) : "l"(p));
    return a;
}
__device__ __forceinline__ float sigf(float x) { return 1.0f / (1.0f + expf(-x)); }

__device__ __forceinline__ uint32_t sw128(uint32_t off) {
    return off ^ ((off >> 3) & 0x70);
}

__device__ __forceinline__ void ldsm4(uint32_t addr, uint32_t* r) {
    asm volatile("ldmatrix.sync.aligned.m8n8.x4.shared.b16 {%0,%1,%2,%3}, [%4];"
        : "=r"(r[0]), "=r"(r[1]), "=r"(r[2]), "=r"(r[3]) : "r"(addr));
}

__device__ __forceinline__ void mma16816(float* d, const uint32_t* a, const uint32_t* b) {
    asm volatile(
        "mma.sync.aligned.m16n8k16.row.col.f32.f16.f16.f32 "
        "{%0,%1,%2,%3}, {%4,%5,%6,%7}, {%8,%9}, {%0,%1,%2,%3};"
        : "+f"(d[0]), "+f"(d[1]), "+f"(d[2]), "+f"(d[3])
        : "r"(a[0]), "r"(a[1]), "r"(a[2]), "r"(a[3]), "r"(b[0]), "r"(b[1]));
}

__device__ __forceinline__ void cpa16(uint32_t dst, const void* src) {
    asm volatile("cp.async.cg.shared.global [%0], [%1], 16;" :: "r"(dst), "l"(src));
}
#define CP_COMMIT() asm volatile("cp.async.commit_group;" ::: "memory")
#define CP_WAIT1()  asm volatile("cp.async.wait_group 1;"  ::: "memory")
#define CP_WAIT0()  asm volatile("cp.async.wait_group 0;"  ::: "memory")

// ---------------- SMEM layout ----------------
// header 1024B: bias[128] floats (gate-major) for the gates kernel
// stage (32KB): A 16KB (128 rows x 128B) | B 16KB (128 rows x 128B), fp16, SW128
// 3 stages; ~97KB/CTA -> 2 CTAs per SM. Epilogue exchange buffer overlays stages.
#define HDR       1024
#define T_A       0
#define T_B       16384
#define STAGE_SZ  32768
#define NSTAGE    3
#define SMEM_TOTAL (HDR + NSTAGE * STAGE_SZ)   // 99328
#define EX_STRIDE 132                           // floats; 128x132x4B = 67.6KB <= 96KB

// async-load one K=64 chunk, single-B-region variant (gemm_out).
__device__ __forceinline__ void load_chunk1(const __half* __restrict__ Ab,
                                            const __half* __restrict__ Bb,
                                            uint32_t stage, int tid) {
    #pragma unroll
    for (int it = 0; it < 4; ++it) {
        int idx = tid + it * 256;
        int r = idx >> 3, c16 = idx & 7;
        cpa16(stage + T_A + sw128((uint32_t)(r * 128 + c16 * 16)),
              Ab + (size_t)r * KDIM + c16 * 8);
    }
    #pragma unroll
    for (int it = 0; it < 4; ++it) {
        int idx = tid + it * 256;
        int r = idx >> 3, c16 = idx & 7;
        cpa16(stage + T_B + sw128((uint32_t)(r * 128 + c16 * 16)),
              Bb + (size_t)r * KDIM + c16 * 8);
    }
}

// async-load one K=64 chunk, 4-gate B gather (gates kernel).
// B tile rows: r in [0,128); gate g = r>>5 selects base, local row = r&31.
// bIters==2 -> only rows [0,64) (i/f gates) are loaded (peephole segment).
__device__ __forceinline__ void load_chunk4(const __half* __restrict__ Ab,
                                            const __half* __restrict__ B0,
                                            const __half* __restrict__ B1,
                                            const __half* __restrict__ B2,
                                            const __half* __restrict__ B3,
                                            uint32_t stage, int tid, int bIters) {
    #pragma unroll
    for (int it = 0; it < 4; ++it) {
        int idx = tid + it * 256;
        int r = idx >> 3, c16 = idx & 7;
        cpa16(stage + T_A + sw128((uint32_t)(r * 128 + c16 * 16)),
              Ab + (size_t)r * KDIM + c16 * 8);
    }
    #pragma unroll
    for (int it = 0; it < 4; ++it) {
        if (it >= bIters) break;
        int idx = tid + it * 256;
        int r = idx >> 3, c16 = idx & 7;
        int g = r >> 5, lr = r & 31;
        const __half* base = (g & 2) ? ((g & 1) ? B3 : B2)
                                     : ((g & 1) ? B1 : B0);
        cpa16(stage + T_B + sw128((uint32_t)(r * 128 + c16 * 16)),
              base + (size_t)lr * KDIM + c16 * 8);
    }
}

// Compute one K=64 chunk (4 k16 steps): warp tile 64(M) x 32(N).
__device__ __forceinline__ void compute_chunk(uint32_t stage_addr, int wm, int wn,
                                              int lane, float (&acc)[4][4][4]) {
    const uint32_t a_base = stage_addr + T_A;
    const uint32_t b_base = stage_addr + T_B;
    const int a_m = lane % 16;
    const int a_k = (lane / 16) * 8;
    const int b_n = (lane / 16) * 8 + (lane % 8);
    const int b_k = ((lane / 8) % 2) * 8;

    #pragma unroll
    for (int kk = 0; kk < 4; ++kk) {
        uint32_t Ah[4][4], Bh[2][4];
        #pragma unroll
        for (int mt = 0; mt < 4; ++mt) {
            uint32_t off = sw128((uint32_t)((wm + mt * 16 + a_m) * 128 + kk * 32 + a_k * 2));
            ldsm4(a_base + off, Ah[mt]);
        }
        #pragma unroll
        for (int nt = 0; nt < 2; ++nt) {
            uint32_t off = sw128((uint32_t)((wn + nt * 16 + b_n) * 128 + kk * 32 + b_k * 2));
            ldsm4(b_base + off, Bh[nt]);
        }
        #pragma unroll
        for (int mt = 0; mt < 4; ++mt)
            #pragma unroll
            for (int n8 = 0; n8 < 4; ++n8)
                mma16816(acc[mt][n8], Ah[mt], &Bh[n8 >> 1][(n8 & 1) * 2]);
    }
}

// ---------------------------------------------------------------------------
// Merged fp32 -> fp16 converter: grid.y selects segment, grid-stride in x.
// ---------------------------------------------------------------------------
struct F2HSeg { const float4* src; uint2* dst; int n4; };

__global__ __launch_bounds__(256)
void f2h_all(F2HSeg s0, F2HSeg s1, F2HSeg s2, F2HSeg s3,
             F2HSeg s4, F2HSeg s5, F2HSeg s6, F2HSeg s7) {
    F2HSeg s;
    switch (blockIdx.y) {
        case 0: s = s0; break; case 1: s = s1; break;
        case 2: s = s2; break; case 3: s = s3; break;
        case 4: s = s4; break; case 5: s = s5; break;
        case 6: s = s6; break; default: s = s7; break;
    }
    const int stride = gridDim.x * blockDim.x;
    for (int i = blockIdx.x * blockDim.x + threadIdx.x; i < s.n4; i += stride) {
        float4 v = s.src[i];
        __half2 h0 = __floats2half2_rn(v.x, v.y);
        __half2 h1 = __floats2half2_rn(v.z, v.w);
        s.dst[i] = make_uint2(*reinterpret_cast<uint32_t*>(&h0),
                              *reinterpret_cast<uint32_t*>(&h1));
    }
}

// ---------------------------------------------------------------------------
// GEMM1 + cell fused. Each CTA: 128 batch rows x 32 output cols x ALL 4 gates.
// Segments: 0=x@w_ih, 1=hx@w_hh (full 128-row B tiles, 4-gate gather),
// 2=cx@w_p{i,f} (HALF tile: only B rows [0,64) = i/f gates; warps with
// wn >= 64 skip compute so g/o accumulators get no peephole term).
// Epilogue: smem exchange -> cell update -> cy (fp32 + fp16) + o-preact.
// grid = (32 m-tiles, 64 col-tiles), block = 256, 2 CTAs/SM.
// ---------------------------------------------------------------------------
__global__ __launch_bounds__(256, 2)
void gemm_gates_cell(const float* __restrict__ b_ih, const float* __restrict__ b_hh,
                     const float* __restrict__ cx,
                     const float* __restrict__ td0, const float* __restrict__ td1,
                     const float* __restrict__ aS,  const float* __restrict__ bS,
                     float* __restrict__ cy_out)
{
    extern __shared__ char sm[];
    const int tid  = threadIdx.x;
    const int wid  = tid >> 5;
    const int lane = tid & 31;
    const int m0   = blockIdx.x * 128;
    const int n0   = blockIdx.y * 32;          // column block within OUTF
    const int wm   = (wid & 1) * 64;
    const int wn   = (wid >> 1) * 32;          // gate-major column in [0,128)

    // bias, gate-major: bsum[g*32 + j] = b_ih[g*OUTF+n0+j] + b_hh[...]
    float* bsum = reinterpret_cast<float*>(sm);
    if (tid < 128) {
        int g = tid >> 5, j = tid & 31;
        bsum[tid] = b_ih[g * OUTF + n0 + j] + b_hh[g * OUTF + n0 + j];
    }

    const uint32_t smb = smem_u32(sm);
    const __half* segA[3];
    segA[0] = g_xh  + (size_t)m0 * KDIM;
    segA[1] = g_hxh + (size_t)m0 * KDIM;
    segA[2] = g_cxh + (size_t)m0 * KDIM;
    // B bases per segment per gate
    const __half* segB[3][4];
    #pragma unroll
    for (int g = 0; g < 4; ++g) {
        segB[0][g] = g_wih + (size_t)(g * OUTF + n0) * KDIM;
        segB[1][g] = g_whh + (size_t)(g * OUTF + n0) * KDIM;
    }
    segB[2][0] = g_wp + (size_t)n0 * KDIM;            // w_pi rows (i gate)
    segB[2][1] = g_wp + (size_t)(OUTF + n0) * KDIM;   // w_pf rows (f gate)
    segB[2][2] = segB[2][0];                          // never loaded (bIters=2)
    segB[2][3] = segB[2][1];                          // never loaded

    float acc[4][4][4];
    #pragma unroll
    for (int i = 0; i < 4; ++i)
        #pragma unroll
        for (int j = 0; j < 4; ++j)
            #pragma unroll
            for (int k = 0; k < 4; ++k) acc[i][j][k] = 0.f;

    const int nch = 3 * 32;

    auto issue = [&](int c) {
        const int seg = c >> 5;
        const int kc  = (c & 31) << 6;
        load_chunk4(segA[seg] + kc,
                    segB[seg][0] + kc, segB[seg][1] + kc,
                    segB[seg][2] + kc, segB[seg][3] + kc,
                    smb + HDR + (uint32_t)(c % NSTAGE) * STAGE_SZ, tid,
                    (seg == 2) ? 2 : 4);
        CP_COMMIT();
    };

    issue(0);
    issue(1);

    for (int c = 0; c < nch; ++c) {
        if (c + 1 < nch) { CP_WAIT1(); } else { CP_WAIT0(); }
        __syncthreads();
        if (c + 2 < nch) issue(c + 2);
        // peephole segment: only i/f-gate warps (wn < 64) compute
        if ((c >> 5) != 2 || wn < 64)
            compute_chunk(smb + HDR + (uint32_t)(c % NSTAGE) * STAGE_SZ, wm, wn, lane, acc);
    }

    // ---- epilogue: exchange through smem, then fused cell update ----
    __syncthreads();   // all compute done; stages reusable as exchange buffer
    float* ex = reinterpret_cast<float*>(sm + HDR);   // [128 rows][EX_STRIDE]

    #pragma unroll
    for (int mt = 0; mt < 4; ++mt) {
        #pragma unroll
        for (int n8 = 0; n8 < 4; ++n8) {
            int bcol = wn + n8 * 8 + (lane % 4) * 2;
            float bx0 = bsum[bcol], bx1 = bsum[bcol + 1];
            int r0 = wm + mt * 16 + lane / 4;
            *reinterpret_cast<float2*>(ex + (size_t)r0 * EX_STRIDE + bcol) =
                make_float2(acc[mt][n8][0] + bx0, acc[mt][n8][1] + bx1);
            *reinterpret_cast<float2*>(ex + (size_t)(r0 + 8) * EX_STRIDE + bcol) =
                make_float2(acc[mt][n8][2] + bx0, acc[mt][n8][3] + bx1);
        }
    }
    __syncthreads();

    // cell: 128 rows x 32 cols; 2 threads per row, 16 cols each (4x float4)
    {
        const int row = tid >> 1;
        const int c0  = (tid & 1) * 16;
        const int gr  = m0 + row;
        const float aa = aS[0], bb = bS[0];
        const float forc = aa * expf(-bb * td0[gr]);
        const float inc  = aa * expf(-bb * td1[gr]);
        const float* exr = ex + (size_t)row * EX_STRIDE;

        #pragma unroll
        for (int j4 = 0; j4 < 4; ++j4) {
            int j = c0 + j4 * 4;
            float4 iv = *reinterpret_cast<const float4*>(exr + j);
            float4 fv = *reinterpret_cast<const float4*>(exr + 32 + j);
            float4 gv = *reinterpret_cast<const float4*>(exr + 64 + j);
            float4 ov = *reinterpret_cast<const float4*>(exr + 96 + j);
            float4 cxv = *reinterpret_cast<const float4*>(cx + (size_t)gr * OUTF + n0 + j);

            float4 cyv;
            cyv.x = forc * sigf(fv.x) * cxv.x + inc * sigf(iv.x) * tanhf(gv.x);
            cyv.y = forc * sigf(fv.y) * cxv.y + inc * sigf(iv.y) * tanhf(gv.y);
            cyv.z = forc * sigf(fv.z) * cxv.z + inc * sigf(iv.z) * tanhf(gv.z);
            cyv.w = forc * sigf(fv.w) * cxv.w + inc * sigf(iv.w) * tanhf(gv.w);

            *reinterpret_cast<float4*>(cy_out + (size_t)gr * OUTF + n0 + j) = cyv;
            __half2 h0 = __floats2half2_rn(cyv.x, cyv.y);
            __half2 h1 = __floats2half2_rn(cyv.z, cyv.w);
            *reinterpret_cast<uint2*>(g_cyh + (size_t)gr * OUTF + n0 + j) =
                make_uint2(*reinterpret_cast<uint32_t*>(&h0),
                           *reinterpret_cast<uint32_t*>(&h1));
            *reinterpret_cast<float4*>(g_gates + (size_t)gr * OUTF + n0 + j) = ov;
        }
    }
}

// ---------------------------------------------------------------------------
// GEMM3: O = cy @ w_po^T ; hy = sigmoid(o_preact + O) * tanh(cy)
// grid = (32 m-tiles, 16 n-tiles), block = 256. CTA tile 128x128, 2 CTAs/SM.
// ---------------------------------------------------------------------------
__global__ __launch_bounds__(256, 2)
void gemm_out(const float* __restrict__ cy, float* __restrict__ hy)
{
    extern __shared__ char sm[];
    const int tid  = threadIdx.x;
    const int wid  = tid >> 5;
    const int lane = tid & 31;
    const int m0   = blockIdx.x * 128;
    const int n0   = blockIdx.y * 128;
    const int wm   = (wid & 1) * 64;
    const int wn   = (wid >> 1) * 32;

    const uint32_t smb = smem_u32(sm);
    const __half* Ab = g_cyh + (size_t)m0 * KDIM;
    const __half* Bb = g_wpo + (size_t)n0 * KDIM;

    float acc[4][4][4];
    #pragma unroll
    for (int i = 0; i < 4; ++i)
        #pragma unroll
        for (int j = 0; j < 4; ++j)
            #pragma unroll
            for (int k = 0; k < 4; ++k) acc[i][j][k] = 0.f;

    const int nch = 32;

    auto issue = [&](int c) {
        const int kc = c << 6;
        load_chunk1(Ab + kc, Bb + kc,
                    smb + HDR + (uint32_t)(c % NSTAGE) * STAGE_SZ, tid);
        CP_COMMIT();
    };

    issue(0);
    issue(1);

    for (int c = 0; c < nch; ++c) {
        if (c + 1 < nch) { CP_WAIT1(); } else { CP_WAIT0(); }
        __syncthreads();
        if (c + 2 < nch) issue(c + 2);
        compute_chunk(smb + HDR + (uint32_t)(c % NSTAGE) * STAGE_SZ, wm, wn, lane, acc);
    }

    // fused epilogue
    #pragma unroll
    for (int mt = 0; mt < 4; ++mt) {
        #pragma unroll
        for (int n8 = 0; n8 < 4; ++n8) {
            int col = n0 + wn + n8 * 8 + (lane % 4) * 2;
            #pragma unroll
            for (int half = 0; half < 2; ++half) {
                int row = m0 + wm + mt * 16 + lane / 4 + half * 8;
                const float* gorow = g_gates + (size_t)row * OUTF + col;
                const float* cyrow = cy + (size_t)row * OUTF + col;
                float*       hyrow = hy + (size_t)row * OUTF + col;
                float2 go  = *reinterpret_cast<const float2*>(gorow);
                float2 cyv = *reinterpret_cast<const float2*>(cyrow);
                float2 r;
                r.x = sigf(go.x + acc[mt][n8][half * 2 + 0]) * tanhf(cyv.x);
                r.y = sigf(go.y + acc[mt][n8][half * 2 + 1]) * tanhf(cyv.y);
                *reinterpret_cast<float2*>(hyrow) = r;
            }
        }
    }
}

// ---------------------------------------------------------------------------
extern "C" void kernel_launch(void* const* d_in, const int* in_sizes, int n_in,
                              void* d_out, int out_size)
{
    (void)in_sizes; (void)n_in; (void)out_size;
    const float* x    = (const float*)d_in[0];
    const float* td0  = (const float*)d_in[1];
    const float* td1  = (const float*)d_in[2];
    const float* hx   = (const float*)d_in[3];
    const float* cx   = (const float*)d_in[4];
    const float* w_ih = (const float*)d_in[5];
    const float* w_hh = (const float*)d_in[6];
    const float* w_pi = (const float*)d_in[7];
    const float* w_pf = (const float*)d_in[8];
    const float* w_po = (const float*)d_in[9];
    const float* b_ih = (const float*)d_in[10];
    const float* b_hh = (const float*)d_in[11];
    const float* aS   = (const float*)d_in[12];
    const float* bS   = (const float*)d_in[13];

    float* out = (float*)d_out;
    float* hy  = out;                        // [B, OUT]
    float* cy  = out + (size_t)BSZ * OUTF;   // [B, OUT]

    // symbol addresses for fp16 buffers
    void *p_xh, *p_hxh, *p_cxh, *p_wih, *p_whh, *p_wp, *p_wpo;
    cudaGetSymbolAddress(&p_xh,  g_xh);
    cudaGetSymbolAddress(&p_hxh, g_hxh);
    cudaGetSymbolAddress(&p_cxh, g_cxh);
    cudaGetSymbolAddress(&p_wih, g_wih);
    cudaGetSymbolAddress(&p_whh, g_whh);
    cudaGetSymbolAddress(&p_wp,  g_wp);
    cudaGetSymbolAddress(&p_wpo, g_wpo);

    const int actN4 = BSZ * KDIM / 4;        // activations
    const int wBigN4 = NG * KDIM / 4;        // w_ih / w_hh
    const int wSmN4 = OUTF * KDIM / 4;       // peephole / output weights

    F2HSeg s0 = {(const float4*)x,    (uint2*)p_xh,  actN4};
    F2HSeg s1 = {(const float4*)hx,   (uint2*)p_hxh, actN4};
    F2HSeg s2 = {(const float4*)cx,   (uint2*)p_cxh, actN4};
    F2HSeg s3 = {(const float4*)w_ih, (uint2*)p_wih, wBigN4};
    F2HSeg s4 = {(const float4*)w_hh, (uint2*)p_whh, wBigN4};
    F2HSeg s5 = {(const float4*)w_pi, (uint2*)p_wp,  wSmN4};
    F2HSeg s6 = {(const float4*)w_pf,
                 (uint2*)((char*)p_wp + (size_t)OUTF * KDIM * sizeof(__half)), wSmN4};
    F2HSeg s7 = {(const float4*)w_po, (uint2*)p_wpo, wSmN4};

    f2h_all<<<dim3(1024, 8), 256>>>(s0, s1, s2, s3, s4, s5, s6, s7);

    cudaFuncSetAttribute(gemm_gates_cell, cudaFuncAttributeMaxDynamicSharedMemorySize, SMEM_TOTAL);
    cudaFuncSetAttribute(gemm_out,        cudaFuncAttributeMaxDynamicSharedMemorySize, SMEM_TOTAL);

    gemm_gates_cell<<<dim3(BSZ / 128, OUTF / 32), 256, SMEM_TOTAL>>>(
        b_ih, b_hh, cx, td0, td1, aS, bS, cy);

    gemm_out<<<dim3(BSZ / 128, OUTF / 128), 256, SMEM_TOTAL>>>(cy, hy);
}

// round 13
// speedup vs baseline: 1.1614x; 1.1361x over previous
#include <cuda_runtime.h>
#include <cuda_fp16.h>
#include <cstdint>
#include <math.h>

#define BSZ  4096
#define OUTF 2048
#define NG   8192
#define KDIM 2048

// fp16 gate pre-activations scratch [B, 4*OUT]
__device__ __half g_gates[(size_t)BSZ * NG];   // 64 MiB

// fp16 copies (filled by prologue converts / cell kernel)
__device__ __half g_xh [(size_t)BSZ * KDIM];
__device__ __half g_hxh[(size_t)BSZ * KDIM];
__device__ __half g_cxh[(size_t)BSZ * KDIM];
__device__ __half g_cyh[(size_t)BSZ * KDIM];
__device__ __half g_wih[(size_t)NG * KDIM];
__device__ __half g_whh[(size_t)NG * KDIM];
__device__ __half g_wp [(size_t)2 * OUTF * KDIM];   // w_pi rows then w_pf rows
__device__ __half g_wpo[(size_t)OUTF * KDIM];

__device__ __forceinline__ uint32_t smem_u32(const void* p) {
    uint32_t a;
    asm("{ .reg .u64 t; cvta.to.shared.u64 t, %1; cvt.u32.u64 %0, t; }" : "=r"(a) : "l"(p));
    return a;
}
__device__ __forceinline__ float sigf(float x) { return 1.0f / (1.0f + expf(-x)); }

__device__ __forceinline__ uint32_t sw128(uint32_t off) {
    return off ^ ((off >> 3) & 0x70);
}

__device__ __forceinline__ void ldsm4(uint32_t addr, uint32_t* r) {
    asm volatile("ldmatrix.sync.aligned.m8n8.x4.shared.b16 {%0,%1,%2,%3}, [%4];"
        : "=r"(r[0]), "=r"(r[1]), "=r"(r[2]), "=r"(r[3]) : "r"(addr));
}

__device__ __forceinline__ void mma16816(float* d, const uint32_t* a, const uint32_t* b) {
    asm volatile(
        "mma.sync.aligned.m16n8k16.row.col.f32.f16.f16.f32 "
        "{%0,%1,%2,%3}, {%4,%5,%6,%7}, {%8,%9}, {%0,%1,%2,%3};"
        : "+f"(d[0]), "+f"(d[1]), "+f"(d[2]), "+f"(d[3])
        : "r"(a[0]), "r"(a[1]), "r"(a[2]), "r"(a[3]), "r"(b[0]), "r"(b[1]));
}

__device__ __forceinline__ void cpa16(uint32_t dst, const void* src) {
    asm volatile("cp.async.cg.shared.global [%0], [%1], 16;" :: "r"(dst), "l"(src));
}
#define CP_COMMIT() asm volatile("cp.async.commit_group;" ::: "memory")
#define CP_WAIT1()  asm volatile("cp.async.wait_group 1;"  ::: "memory")
#define CP_WAIT0()  asm volatile("cp.async.wait_group 0;"  ::: "memory")

// ---------------- SMEM layout ----------------
// header 1024B: bias[128] floats (gates kernel only)
// stage (32KB): A 16KB (128 rows x 128B) | B 16KB (128 rows x 128B), fp16, SW128
// 3 stages; ~97KB/CTA -> 2 CTAs per SM.
#define HDR       1024
#define T_A       0
#define T_B       16384
#define STAGE_SZ  32768
#define NSTAGE    3
#define SMEM_TOTAL (HDR + NSTAGE * STAGE_SZ)   // 99328

// async-load one K=64 chunk: A 128 rows, B 128 rows (fp16 global, row stride KDIM)
__device__ __forceinline__ void load_chunk(const __half* __restrict__ Ab,
                                           const __half* __restrict__ Bb,
                                           uint32_t stage, int tid) {
    #pragma unroll
    for (int it = 0; it < 4; ++it) {
        int idx = tid + it * 256;
        int r = idx >> 3, c16 = idx & 7;
        cpa16(stage + T_A + sw128((uint32_t)(r * 128 + c16 * 16)),
              Ab + (size_t)r * KDIM + c16 * 8);
    }
    #pragma unroll
    for (int it = 0; it < 4; ++it) {
        int idx = tid + it * 256;
        int r = idx >> 3, c16 = idx & 7;
        cpa16(stage + T_B + sw128((uint32_t)(r * 128 + c16 * 16)),
              Bb + (size_t)r * KDIM + c16 * 8);
    }
}

// Compute one K=64 chunk (4 k16 steps): warp tile 64(M) x 32(N).
__device__ __forceinline__ void compute_chunk(uint32_t stage_addr, int wm, int wn,
                                              int lane, float (&acc)[4][4][4]) {
    const uint32_t a_base = stage_addr + T_A;
    const uint32_t b_base = stage_addr + T_B;
    const int a_m = lane % 16;
    const int a_k = (lane / 16) * 8;
    const int b_n = (lane / 16) * 8 + (lane % 8);
    const int b_k = ((lane / 8) % 2) * 8;

    #pragma unroll
    for (int kk = 0; kk < 4; ++kk) {
        uint32_t Ah[4][4], Bh[2][4];
        #pragma unroll
        for (int mt = 0; mt < 4; ++mt) {
            uint32_t off = sw128((uint32_t)((wm + mt * 16 + a_m) * 128 + kk * 32 + a_k * 2));
            ldsm4(a_base + off, Ah[mt]);
        }
        #pragma unroll
        for (int nt = 0; nt < 2; ++nt) {
            uint32_t off = sw128((uint32_t)((wn + nt * 16 + b_n) * 128 + kk * 32 + b_k * 2));
            ldsm4(b_base + off, Bh[nt]);
        }
        #pragma unroll
        for (int mt = 0; mt < 4; ++mt)
            #pragma unroll
            for (int n8 = 0; n8 < 4; ++n8)
                mma16816(acc[mt][n8], Ah[mt], &Bh[n8 >> 1][(n8 & 1) * 2]);
    }
}

// ---------------------------------------------------------------------------
// Merged fp32 -> fp16 converter: grid.y selects segment, grid-stride in x.
// ---------------------------------------------------------------------------
struct F2HSeg { const float4* src; uint2* dst; int n4; };

__global__ __launch_bounds__(256)
void f2h_all(F2HSeg s0, F2HSeg s1, F2HSeg s2, F2HSeg s3,
             F2HSeg s4, F2HSeg s5, F2HSeg s6, F2HSeg s7) {
    F2HSeg s;
    switch (blockIdx.y) {
        case 0: s = s0; break; case 1: s = s1; break;
        case 2: s = s2; break; case 3: s = s3; break;
        case 4: s = s4; break; case 5: s = s5; break;
        case 6: s = s6; break; default: s = s7; break;
    }
    const int stride = gridDim.x * blockDim.x;
    for (int i = blockIdx.x * blockDim.x + threadIdx.x; i < s.n4; i += stride) {
        float4 v = s.src[i];
        __half2 h0 = __floats2half2_rn(v.x, v.y);
        __half2 h1 = __floats2half2_rn(v.z, v.w);
        s.dst[i] = make_uint2(*reinterpret_cast<uint32_t*>(&h0),
                              *reinterpret_cast<uint32_t*>(&h1));
    }
}

// ---------------------------------------------------------------------------
// GEMM1: gates[B, 8192] = x@w_ih^T + hx@w_hh^T (+ cx@w_p{i,f}^T) + biases
// grid = (32 m-tiles, 64 n-tiles), block = 256. CTA tile 128x128, 2 CTAs/SM.
// Gate preactivations stored fp16.
// ---------------------------------------------------------------------------
__global__ __launch_bounds__(256, 2)
void gemm_gates(const float* __restrict__ b_ih, const float* __restrict__ b_hh)
{
    extern __shared__ char sm[];
    const int tid  = threadIdx.x;
    const int wid  = tid >> 5;
    const int lane = tid & 31;
    const int m0   = blockIdx.x * 128;
    const int n0   = blockIdx.y * 128;
    const int wm   = (wid & 1) * 64;
    const int wn   = (wid >> 1) * 32;

    float* bsum = reinterpret_cast<float*>(sm);
    if (tid < 128) bsum[tid] = b_ih[n0 + tid] + b_hh[n0 + tid];

    const uint32_t smb = smem_u32(sm);
    const int nseg = (n0 < 2 * OUTF) ? 3 : 2;
    const __half* segA[3];
    const __half* segB[3];
    segA[0] = g_xh  + (size_t)m0 * KDIM; segB[0] = g_wih + (size_t)n0 * KDIM;
    segA[1] = g_hxh + (size_t)m0 * KDIM; segB[1] = g_whh + (size_t)n0 * KDIM;
    segA[2] = g_cxh + (size_t)m0 * KDIM; segB[2] = g_wp  + (size_t)n0 * KDIM;

    float acc[4][4][4];
    #pragma unroll
    for (int i = 0; i < 4; ++i)
        #pragma unroll
        for (int j = 0; j < 4; ++j)
            #pragma unroll
            for (int k = 0; k < 4; ++k) acc[i][j][k] = 0.f;

    const int nch = nseg * 32;

    auto issue = [&](int c) {
        const int seg = c >> 5;
        const int kc  = (c & 31) << 6;
        load_chunk(segA[seg] + kc, segB[seg] + kc,
                   smb + HDR + (uint32_t)(c % NSTAGE) * STAGE_SZ, tid);
        CP_COMMIT();
    };

    issue(0);
    issue(1);

    for (int c = 0; c < nch; ++c) {
        if (c + 1 < nch) { CP_WAIT1(); } else { CP_WAIT0(); }
        __syncthreads();
        if (c + 2 < nch) issue(c + 2);
        compute_chunk(smb + HDR + (uint32_t)(c % NSTAGE) * STAGE_SZ, wm, wn, lane, acc);
    }

    // epilogue: bias + store fp16 preacts
    #pragma unroll
    for (int mt = 0; mt < 4; ++mt) {
        #pragma unroll
        for (int n8 = 0; n8 < 4; ++n8) {
            int lcol = wn + n8 * 8 + (lane % 4) * 2;
            float bx0 = bsum[lcol], bx1 = bsum[lcol + 1];
            int r0 = m0 + wm + mt * 16 + lane / 4;
            __half* g0 = g_gates + (size_t)r0 * NG + n0 + lcol;
            __half* g1 = g_gates + (size_t)(r0 + 8) * NG + n0 + lcol;
            *reinterpret_cast<__half2*>(g0) =
                __floats2half2_rn(acc[mt][n8][0] + bx0, acc[mt][n8][1] + bx1);
            *reinterpret_cast<__half2*>(g1) =
                __floats2half2_rn(acc[mt][n8][2] + bx0, acc[mt][n8][3] + bx1);
        }
    }
}

// ---------------------------------------------------------------------------
// Cell update: cy = a*exp(-b*td0)*sig(f)*cx + a*exp(-b*td1)*sig(i)*tanh(g)
// Reads fp16 preacts; writes cy fp32 (d_out) and cy fp16 (g_cyh).
// 8 elements per thread.
// ---------------------------------------------------------------------------
__device__ __forceinline__ void unpack8(uint4 u, float* o) {
    float2 t;
    t = __half22float2(*reinterpret_cast<__half2*>(&u.x)); o[0] = t.x; o[1] = t.y;
    t = __half22float2(*reinterpret_cast<__half2*>(&u.y)); o[2] = t.x; o[3] = t.y;
    t = __half22float2(*reinterpret_cast<__half2*>(&u.z)); o[4] = t.x; o[5] = t.y;
    t = __half22float2(*reinterpret_cast<__half2*>(&u.w)); o[6] = t.x; o[7] = t.y;
}

__global__ __launch_bounds__(256)
void cell_kernel(const float* __restrict__ cx,
                 const float* __restrict__ td0, const float* __restrict__ td1,
                 const float* __restrict__ aS,  const float* __restrict__ bS,
                 float* __restrict__ cy_out)
{
    size_t idx = (size_t)blockIdx.x * blockDim.x + threadIdx.x;
    const size_t total = (size_t)BSZ * OUTF / 8;
    if (idx >= total) return;
    int row = (int)(idx / (OUTF / 8));
    int c   = (int)(idx % (OUTF / 8)) * 8;

    float a = aS[0], b = bS[0];
    float forc = a * expf(-b * td0[row]);
    float inc  = a * expf(-b * td1[row]);

    const __half* grow = g_gates + (size_t)row * NG;
    float iv[8], fv[8], gv[8];
    unpack8(*reinterpret_cast<const uint4*>(grow + c),            iv);
    unpack8(*reinterpret_cast<const uint4*>(grow + OUTF + c),     fv);
    unpack8(*reinterpret_cast<const uint4*>(grow + 2 * OUTF + c), gv);

    const float* cxp = cx + (size_t)row * OUTF + c;
    float4 cx0 = *reinterpret_cast<const float4*>(cxp);
    float4 cx1 = *reinterpret_cast<const float4*>(cxp + 4);
    float cxv[8] = {cx0.x, cx0.y, cx0.z, cx0.w, cx1.x, cx1.y, cx1.z, cx1.w};

    float cyv[8];
    #pragma unroll
    for (int j = 0; j < 8; ++j)
        cyv[j] = forc * sigf(fv[j]) * cxv[j] + inc * sigf(iv[j]) * tanhf(gv[j]);

    float* cyp = cy_out + (size_t)row * OUTF + c;
    *reinterpret_cast<float4*>(cyp)     = make_float4(cyv[0], cyv[1], cyv[2], cyv[3]);
    *reinterpret_cast<float4*>(cyp + 4) = make_float4(cyv[4], cyv[5], cyv[6], cyv[7]);

    __half2 h0 = __floats2half2_rn(cyv[0], cyv[1]);
    __half2 h1 = __floats2half2_rn(cyv[2], cyv[3]);
    __half2 h2 = __floats2half2_rn(cyv[4], cyv[5]);
    __half2 h3 = __floats2half2_rn(cyv[6], cyv[7]);
    uint4 packed;
    packed.x = *reinterpret_cast<uint32_t*>(&h0);
    packed.y = *reinterpret_cast<uint32_t*>(&h1);
    packed.z = *reinterpret_cast<uint32_t*>(&h2);
    packed.w = *reinterpret_cast<uint32_t*>(&h3);
    *reinterpret_cast<uint4*>(g_cyh + (size_t)row * OUTF + c) = packed;
}

// ---------------------------------------------------------------------------
// GEMM3: O = cy @ w_po^T ; hy = sigmoid(o_preact + O) * tanh(cy)
// grid = (32 m-tiles, 16 n-tiles), block = 256. CTA tile 128x128, 2 CTAs/SM.
// ---------------------------------------------------------------------------
__global__ __launch_bounds__(256, 2)
void gemm_out(const float* __restrict__ cy, float* __restrict__ hy)
{
    extern __shared__ char sm[];
    const int tid  = threadIdx.x;
    const int wid  = tid >> 5;
    const int lane = tid & 31;
    const int m0   = blockIdx.x * 128;
    const int n0   = blockIdx.y * 128;
    const int wm   = (wid & 1) * 64;
    const int wn   = (wid >> 1) * 32;

    const uint32_t smb = smem_u32(sm);
    const __half* Ab = g_cyh + (size_t)m0 * KDIM;
    const __half* Bb = g_wpo + (size_t)n0 * KDIM;

    float acc[4][4][4];
    #pragma unroll
    for (int i = 0; i < 4; ++i)
        #pragma unroll
        for (int j = 0; j < 4; ++j)
            #pragma unroll
            for (int k = 0; k < 4; ++k) acc[i][j][k] = 0.f;

    const int nch = 32;

    auto issue = [&](int c) {
        const int kc = c << 6;
        load_chunk(Ab + kc, Bb + kc,
                   smb + HDR + (uint32_t)(c % NSTAGE) * STAGE_SZ, tid);
        CP_COMMIT();
    };

    issue(0);
    issue(1);

    for (int c = 0; c < nch; ++c) {
        if (c + 1 < nch) { CP_WAIT1(); } else { CP_WAIT0(); }
        __syncthreads();
        if (c + 2 < nch) issue(c + 2);
        compute_chunk(smb + HDR + (uint32_t)(c % NSTAGE) * STAGE_SZ, wm, wn, lane, acc);
    }

    // fused epilogue (o preacts are fp16)
    #pragma unroll
    for (int mt = 0; mt < 4; ++mt) {
        #pragma unroll
        for (int n8 = 0; n8 < 4; ++n8) {
            int col = n0 + wn + n8 * 8 + (lane % 4) * 2;
            #pragma unroll
            for (int half = 0; half < 2; ++half) {
                int row = m0 + wm + mt * 16 + lane / 4 + half * 8;
                const __half* gorow = g_gates + (size_t)row * NG + 3 * OUTF + col;
                const float* cyrow = cy + (size_t)row * OUTF + col;
                float*       hyrow = hy + (size_t)row * OUTF + col;
                float2 go  = __half22float2(*reinterpret_cast<const __half2*>(gorow));
                float2 cyv = *reinterpret_cast<const float2*>(cyrow);
                float2 r;
                r.x = sigf(go.x + acc[mt][n8][half * 2 + 0]) * tanhf(cyv.x);
                r.y = sigf(go.y + acc[mt][n8][half * 2 + 1]) * tanhf(cyv.y);
                *reinterpret_cast<float2*>(hyrow) = r;
            }
        }
    }
}

// ---------------------------------------------------------------------------
extern "C" void kernel_launch(void* const* d_in, const int* in_sizes, int n_in,
                              void* d_out, int out_size)
{
    (void)in_sizes; (void)n_in; (void)out_size;
    const float* x    = (const float*)d_in[0];
    const float* td0  = (const float*)d_in[1];
    const float* td1  = (const float*)d_in[2];
    const float* hx   = (const float*)d_in[3];
    const float* cx   = (const float*)d_in[4];
    const float* w_ih = (const float*)d_in[5];
    const float* w_hh = (const float*)d_in[6];
    const float* w_pi = (const float*)d_in[7];
    const float* w_pf = (const float*)d_in[8];
    const float* w_po = (const float*)d_in[9];
    const float* b_ih = (const float*)d_in[10];
    const float* b_hh = (const float*)d_in[11];
    const float* aS   = (const float*)d_in[12];
    const float* bS   = (const float*)d_in[13];

    float* out = (float*)d_out;
    float* hy  = out;                        // [B, OUT]
    float* cy  = out + (size_t)BSZ * OUTF;   // [B, OUT]

    // symbol addresses for fp16 buffers
    void *p_xh, *p_hxh, *p_cxh, *p_wih, *p_whh, *p_wp, *p_wpo;
    cudaGetSymbolAddress(&p_xh,  g_xh);
    cudaGetSymbolAddress(&p_hxh, g_hxh);
    cudaGetSymbolAddress(&p_cxh, g_cxh);
    cudaGetSymbolAddress(&p_wih, g_wih);
    cudaGetSymbolAddress(&p_whh, g_whh);
    cudaGetSymbolAddress(&p_wp,  g_wp);
    cudaGetSymbolAddress(&p_wpo, g_wpo);

    const int actN4 = BSZ * KDIM / 4;        // activations
    const int wBigN4 = NG * KDIM / 4;        // w_ih / w_hh
    const int wSmN4 = OUTF * KDIM / 4;       // peephole / output weights

    F2HSeg s0 = {(const float4*)x,    (uint2*)p_xh,  actN4};
    F2HSeg s1 = {(const float4*)hx,   (uint2*)p_hxh, actN4};
    F2HSeg s2 = {(const float4*)cx,   (uint2*)p_cxh, actN4};
    F2HSeg s3 = {(const float4*)w_ih, (uint2*)p_wih, wBigN4};
    F2HSeg s4 = {(const float4*)w_hh, (uint2*)p_whh, wBigN4};
    F2HSeg s5 = {(const float4*)w_pi, (uint2*)p_wp,  wSmN4};
    F2HSeg s6 = {(const float4*)w_pf,
                 (uint2*)((char*)p_wp + (size_t)OUTF * KDIM * sizeof(__half)), wSmN4};
    F2HSeg s7 = {(const float4*)w_po, (uint2*)p_wpo, wSmN4};

    f2h_all<<<dim3(1024, 8), 256>>>(s0, s1, s2, s3, s4, s5, s6, s7);

    cudaFuncSetAttribute(gemm_gates, cudaFuncAttributeMaxDynamicSharedMemorySize, SMEM_TOTAL);
    cudaFuncSetAttribute(gemm_out,   cudaFuncAttributeMaxDynamicSharedMemorySize, SMEM_TOTAL);

    gemm_gates<<<dim3(BSZ / 128, NG / 128), 256, SMEM_TOTAL>>>(b_ih, b_hh);

    cell_kernel<<<(BSZ * OUTF / 8 + 255) / 256, 256>>>(cx, td0, td1, aS, bS, cy);

    gemm_out<<<dim3(BSZ / 128, OUTF / 128), 256, SMEM_TOTAL>>>(cy, hy);
}

// round 14
// speedup vs baseline: 1.1651x; 1.0032x over previous
#include <cuda_runtime.h>
#include <cuda_fp16.h>
#include <cstdint>
#include <math.h>

#define BSZ  4096
#define OUTF 2048
#define NG   8192
#define KDIM 2048

// fp16 gate pre-activations scratch [B, 4*OUT]
__device__ __half g_gates[(size_t)BSZ * NG];   // 64 MiB

// fp16 copies (filled by prologue converts / cell kernel)
__device__ __half g_xh [(size_t)BSZ * KDIM];
__device__ __half g_hxh[(size_t)BSZ * KDIM];
__device__ __half g_cxh[(size_t)BSZ * KDIM];
__device__ __half g_cyh[(size_t)BSZ * KDIM];
__device__ __half g_wih[(size_t)NG * KDIM];
__device__ __half g_whh[(size_t)NG * KDIM];
__device__ __half g_wp [(size_t)2 * OUTF * KDIM];   // w_pi rows then w_pf rows
__device__ __half g_wpo[(size_t)OUTF * KDIM];

__device__ __forceinline__ uint32_t smem_u32(const void* p) {
    uint32_t a;
    asm("{ .reg .u64 t; cvta.to.shared.u64 t, %1; cvt.u32.u64 %0, t; }" : "=r"(a) : "l"(p));
    return a;
}
__device__ __forceinline__ float sigf(float x) { return 1.0f / (1.0f + expf(-x)); }

__device__ __forceinline__ uint32_t sw128(uint32_t off) {
    return off ^ ((off >> 3) & 0x70);
}

__device__ __forceinline__ void ldsm4(uint32_t addr, uint32_t* r) {
    asm volatile("ldmatrix.sync.aligned.m8n8.x4.shared.b16 {%0,%1,%2,%3}, [%4];"
        : "=r"(r[0]), "=r"(r[1]), "=r"(r[2]), "=r"(r[3]) : "r"(addr));
}

__device__ __forceinline__ void mma16816(float* d, const uint32_t* a, const uint32_t* b) {
    asm volatile(
        "mma.sync.aligned.m16n8k16.row.col.f32.f16.f16.f32 "
        "{%0,%1,%2,%3}, {%4,%5,%6,%7}, {%8,%9}, {%0,%1,%2,%3};"
        : "+f"(d[0]), "+f"(d[1]), "+f"(d[2]), "+f"(d[3])
        : "r"(a[0]), "r"(a[1]), "r"(a[2]), "r"(a[3]), "r"(b[0]), "r"(b[1]));
}

__device__ __forceinline__ void cpa16(uint32_t dst, const void* src) {
    asm volatile("cp.async.cg.shared.global [%0], [%1], 16;" :: "r"(dst), "l"(src));
}
#define CP_COMMIT() asm volatile("cp.async.commit_group;" ::: "memory")
#define CP_WAIT1()  asm volatile("cp.async.wait_group 1;"  ::: "memory")
#define CP_WAIT0()  asm volatile("cp.async.wait_group 0;"  ::: "memory")

// ---------------- SMEM layout ----------------
// header 1024B: bias[128] floats (gates kernel only)
// stage (32KB): A 16KB (128 rows x 128B) | B 16KB (128 rows x 128B), fp16, SW128
// 3 stages; ~97KB/CTA -> 2 CTAs per SM.
#define HDR       1024
#define T_A       0
#define T_B       16384
#define STAGE_SZ  32768
#define NSTAGE    3
#define SMEM_TOTAL (HDR + NSTAGE * STAGE_SZ)   // 99328

// async-load one K=64 chunk: A 128 rows, B 128 rows (fp16 global, row stride KDIM)
__device__ __forceinline__ void load_chunk(const __half* __restrict__ Ab,
                                           const __half* __restrict__ Bb,
                                           uint32_t stage, int tid) {
    #pragma unroll
    for (int it = 0; it < 4; ++it) {
        int idx = tid + it * 256;
        int r = idx >> 3, c16 = idx & 7;
        cpa16(stage + T_A + sw128((uint32_t)(r * 128 + c16 * 16)),
              Ab + (size_t)r * KDIM + c16 * 8);
    }
    #pragma unroll
    for (int it = 0; it < 4; ++it) {
        int idx = tid + it * 256;
        int r = idx >> 3, c16 = idx & 7;
        cpa16(stage + T_B + sw128((uint32_t)(r * 128 + c16 * 16)),
              Bb + (size_t)r * KDIM + c16 * 8);
    }
}

// Compute one K=64 chunk (4 k16 steps): warp tile 64(M) x 32(N).
__device__ __forceinline__ void compute_chunk(uint32_t stage_addr, int wm, int wn,
                                              int lane, float (&acc)[4][4][4]) {
    const uint32_t a_base = stage_addr + T_A;
    const uint32_t b_base = stage_addr + T_B;
    const int a_m = lane % 16;
    const int a_k = (lane / 16) * 8;
    const int b_n = (lane / 16) * 8 + (lane % 8);
    const int b_k = ((lane / 8) % 2) * 8;

    #pragma unroll
    for (int kk = 0; kk < 4; ++kk) {
        uint32_t Ah[4][4], Bh[2][4];
        #pragma unroll
        for (int mt = 0; mt < 4; ++mt) {
            uint32_t off = sw128((uint32_t)((wm + mt * 16 + a_m) * 128 + kk * 32 + a_k * 2));
            ldsm4(a_base + off, Ah[mt]);
        }
        #pragma unroll
        for (int nt = 0; nt < 2; ++nt) {
            uint32_t off = sw128((uint32_t)((wn + nt * 16 + b_n) * 128 + kk * 32 + b_k * 2));
            ldsm4(b_base + off, Bh[nt]);
        }
        #pragma unroll
        for (int mt = 0; mt < 4; ++mt)
            #pragma unroll
            for (int n8 = 0; n8 < 4; ++n8)
                mma16816(acc[mt][n8], Ah[mt], &Bh[n8 >> 1][(n8 & 1) * 2]);
    }
}

// ---------------------------------------------------------------------------
// Merged fp32 -> fp16 converter: 8 floats per thread, single 16B store.
// grid.y selects segment, grid-stride in x (units of 8 floats).
// ---------------------------------------------------------------------------
struct F2HSeg { const float4* src; uint4* dst; int n8; };

__global__ __launch_bounds__(256)
void f2h_all(F2HSeg s0, F2HSeg s1, F2HSeg s2, F2HSeg s3,
             F2HSeg s4, F2HSeg s5, F2HSeg s6, F2HSeg s7) {
    F2HSeg s;
    switch (blockIdx.y) {
        case 0: s = s0; break; case 1: s = s1; break;
        case 2: s = s2; break; case 3: s = s3; break;
        case 4: s = s4; break; case 5: s = s5; break;
        case 6: s = s6; break; default: s = s7; break;
    }
    const int stride = gridDim.x * blockDim.x;
    for (int i = blockIdx.x * blockDim.x + threadIdx.x; i < s.n8; i += stride) {
        float4 v0 = s.src[i * 2];
        float4 v1 = s.src[i * 2 + 1];
        __half2 h0 = __floats2half2_rn(v0.x, v0.y);
        __half2 h1 = __floats2half2_rn(v0.z, v0.w);
        __half2 h2 = __floats2half2_rn(v1.x, v1.y);
        __half2 h3 = __floats2half2_rn(v1.z, v1.w);
        uint4 o;
        o.x = *reinterpret_cast<uint32_t*>(&h0);
        o.y = *reinterpret_cast<uint32_t*>(&h1);
        o.z = *reinterpret_cast<uint32_t*>(&h2);
        o.w = *reinterpret_cast<uint32_t*>(&h3);
        s.dst[i] = o;
    }
}

// ---------------------------------------------------------------------------
// GEMM1: gates[B, 8192] = x@w_ih^T + hx@w_hh^T (+ cx@w_p{i,f}^T) + biases
// grid = (32 m-tiles, 64 n-tiles), block = 256. CTA tile 128x128, 2 CTAs/SM.
// Gate preactivations stored fp16.
// ---------------------------------------------------------------------------
__global__ __launch_bounds__(256, 2)
void gemm_gates(const float* __restrict__ b_ih, const float* __restrict__ b_hh)
{
    extern __shared__ char sm[];
    const int tid  = threadIdx.x;
    const int wid  = tid >> 5;
    const int lane = tid & 31;
    const int m0   = blockIdx.x * 128;
    const int n0   = blockIdx.y * 128;
    const int wm   = (wid & 1) * 64;
    const int wn   = (wid >> 1) * 32;

    float* bsum = reinterpret_cast<float*>(sm);
    if (tid < 128) bsum[tid] = b_ih[n0 + tid] + b_hh[n0 + tid];

    const uint32_t smb = smem_u32(sm);
    const int nseg = (n0 < 2 * OUTF) ? 3 : 2;
    const __half* segA[3];
    const __half* segB[3];
    segA[0] = g_xh  + (size_t)m0 * KDIM; segB[0] = g_wih + (size_t)n0 * KDIM;
    segA[1] = g_hxh + (size_t)m0 * KDIM; segB[1] = g_whh + (size_t)n0 * KDIM;
    segA[2] = g_cxh + (size_t)m0 * KDIM; segB[2] = g_wp  + (size_t)n0 * KDIM;

    float acc[4][4][4];
    #pragma unroll
    for (int i = 0; i < 4; ++i)
        #pragma unroll
        for (int j = 0; j < 4; ++j)
            #pragma unroll
            for (int k = 0; k < 4; ++k) acc[i][j][k] = 0.f;

    const int nch = nseg * 32;

    auto issue = [&](int c) {
        const int seg = c >> 5;
        const int kc  = (c & 31) << 6;
        load_chunk(segA[seg] + kc, segB[seg] + kc,
                   smb + HDR + (uint32_t)(c % NSTAGE) * STAGE_SZ, tid);
        CP_COMMIT();
    };

    issue(0);
    issue(1);

    for (int c = 0; c < nch; ++c) {
        if (c + 1 < nch) { CP_WAIT1(); } else { CP_WAIT0(); }
        __syncthreads();
        if (c + 2 < nch) issue(c + 2);
        compute_chunk(smb + HDR + (uint32_t)(c % NSTAGE) * STAGE_SZ, wm, wn, lane, acc);
    }

    // epilogue: bias + store fp16 preacts
    #pragma unroll
    for (int mt = 0; mt < 4; ++mt) {
        #pragma unroll
        for (int n8 = 0; n8 < 4; ++n8) {
            int lcol = wn + n8 * 8 + (lane % 4) * 2;
            float bx0 = bsum[lcol], bx1 = bsum[lcol + 1];
            int r0 = m0 + wm + mt * 16 + lane / 4;
            __half* g0 = g_gates + (size_t)r0 * NG + n0 + lcol;
            __half* g1 = g_gates + (size_t)(r0 + 8) * NG + n0 + lcol;
            *reinterpret_cast<__half2*>(g0) =
                __floats2half2_rn(acc[mt][n8][0] + bx0, acc[mt][n8][1] + bx1);
            *reinterpret_cast<__half2*>(g1) =
                __floats2half2_rn(acc[mt][n8][2] + bx0, acc[mt][n8][3] + bx1);
        }
    }
}

// ---------------------------------------------------------------------------
// Cell update: cy = a*exp(-b*td0)*sig(f)*cx + a*exp(-b*td1)*sig(i)*tanh(g)
// Reads fp16 preacts + fp16 cx; writes cy fp32 (d_out) and cy fp16 (g_cyh).
// 8 elements per thread.
// ---------------------------------------------------------------------------
__device__ __forceinline__ void unpack8(uint4 u, float* o) {
    float2 t;
    t = __half22float2(*reinterpret_cast<__half2*>(&u.x)); o[0] = t.x; o[1] = t.y;
    t = __half22float2(*reinterpret_cast<__half2*>(&u.y)); o[2] = t.x; o[3] = t.y;
    t = __half22float2(*reinterpret_cast<__half2*>(&u.z)); o[4] = t.x; o[5] = t.y;
    t = __half22float2(*reinterpret_cast<__half2*>(&u.w)); o[6] = t.x; o[7] = t.y;
}

__global__ __launch_bounds__(256)
void cell_kernel(const float* __restrict__ td0, const float* __restrict__ td1,
                 const float* __restrict__ aS,  const float* __restrict__ bS,
                 float* __restrict__ cy_out)
{
    size_t idx = (size_t)blockIdx.x * blockDim.x + threadIdx.x;
    const size_t total = (size_t)BSZ * OUTF / 8;
    if (idx >= total) return;
    int row = (int)(idx / (OUTF / 8));
    int c   = (int)(idx % (OUTF / 8)) * 8;

    float a = aS[0], b = bS[0];
    float forc = a * expf(-b * td0[row]);
    float inc  = a * expf(-b * td1[row]);

    const __half* grow = g_gates + (size_t)row * NG;
    float iv[8], fv[8], gv[8], cxv[8];
    unpack8(*reinterpret_cast<const uint4*>(grow + c),            iv);
    unpack8(*reinterpret_cast<const uint4*>(grow + OUTF + c),     fv);
    unpack8(*reinterpret_cast<const uint4*>(grow + 2 * OUTF + c), gv);
    unpack8(*reinterpret_cast<const uint4*>(g_cxh + (size_t)row * OUTF + c), cxv);

    float cyv[8];
    #pragma unroll
    for (int j = 0; j < 8; ++j)
        cyv[j] = forc * sigf(fv[j]) * cxv[j] + inc * sigf(iv[j]) * tanhf(gv[j]);

    float* cyp = cy_out + (size_t)row * OUTF + c;
    *reinterpret_cast<float4*>(cyp)     = make_float4(cyv[0], cyv[1], cyv[2], cyv[3]);
    *reinterpret_cast<float4*>(cyp + 4) = make_float4(cyv[4], cyv[5], cyv[6], cyv[7]);

    __half2 h0 = __floats2half2_rn(cyv[0], cyv[1]);
    __half2 h1 = __floats2half2_rn(cyv[2], cyv[3]);
    __half2 h2 = __floats2half2_rn(cyv[4], cyv[5]);
    __half2 h3 = __floats2half2_rn(cyv[6], cyv[7]);
    uint4 packed;
    packed.x = *reinterpret_cast<uint32_t*>(&h0);
    packed.y = *reinterpret_cast<uint32_t*>(&h1);
    packed.z = *reinterpret_cast<uint32_t*>(&h2);
    packed.w = *reinterpret_cast<uint32_t*>(&h3);
    *reinterpret_cast<uint4*>(g_cyh + (size_t)row * OUTF + c) = packed;
}

// ---------------------------------------------------------------------------
// GEMM3: O = cy @ w_po^T ; hy = sigmoid(o_preact + O) * tanh(cy)
// Epilogue reads cy fp16 (g_cyh) and o-preact fp16.
// grid = (32 m-tiles, 16 n-tiles), block = 256. CTA tile 128x128, 2 CTAs/SM.
// ---------------------------------------------------------------------------
__global__ __launch_bounds__(256, 2)
void gemm_out(float* __restrict__ hy)
{
    extern __shared__ char sm[];
    const int tid  = threadIdx.x;
    const int wid  = tid >> 5;
    const int lane = tid & 31;
    const int m0   = blockIdx.x * 128;
    const int n0   = blockIdx.y * 128;
    const int wm   = (wid & 1) * 64;
    const int wn   = (wid >> 1) * 32;

    const uint32_t smb = smem_u32(sm);
    const __half* Ab = g_cyh + (size_t)m0 * KDIM;
    const __half* Bb = g_wpo + (size_t)n0 * KDIM;

    float acc[4][4][4];
    #pragma unroll
    for (int i = 0; i < 4; ++i)
        #pragma unroll
        for (int j = 0; j < 4; ++j)
            #pragma unroll
            for (int k = 0; k < 4; ++k) acc[i][j][k] = 0.f;

    const int nch = 32;

    auto issue = [&](int c) {
        const int kc = c << 6;
        load_chunk(Ab + kc, Bb + kc,
                   smb + HDR + (uint32_t)(c % NSTAGE) * STAGE_SZ, tid);
        CP_COMMIT();
    };

    issue(0);
    issue(1);

    for (int c = 0; c < nch; ++c) {
        if (c + 1 < nch) { CP_WAIT1(); } else { CP_WAIT0(); }
        __syncthreads();
        if (c + 2 < nch) issue(c + 2);
        compute_chunk(smb + HDR + (uint32_t)(c % NSTAGE) * STAGE_SZ, wm, wn, lane, acc);
    }

    // fused epilogue (o preacts fp16, cy fp16)
    #pragma unroll
    for (int mt = 0; mt < 4; ++mt) {
        #pragma unroll
        for (int n8 = 0; n8 < 4; ++n8) {
            int col = n0 + wn + n8 * 8 + (lane % 4) * 2;
            #pragma unroll
            for (int half = 0; half < 2; ++half) {
                int row = m0 + wm + mt * 16 + lane / 4 + half * 8;
                const __half* gorow = g_gates + (size_t)row * NG + 3 * OUTF + col;
                const __half* cyrow = g_cyh + (size_t)row * OUTF + col;
                float*        hyrow = hy + (size_t)row * OUTF + col;
                float2 go  = __half22float2(*reinterpret_cast<const __half2*>(gorow));
                float2 cyv = __half22float2(*reinterpret_cast<const __half2*>(cyrow));
                float2 r;
                r.x = sigf(go.x + acc[mt][n8][half * 2 + 0]) * tanhf(cyv.x);
                r.y = sigf(go.y + acc[mt][n8][half * 2 + 1]) * tanhf(cyv.y);
                *reinterpret_cast<float2*>(hyrow) = r;
            }
        }
    }
}

// ---------------------------------------------------------------------------
extern "C" void kernel_launch(void* const* d_in, const int* in_sizes, int n_in,
                              void* d_out, int out_size)
{
    (void)in_sizes; (void)n_in; (void)out_size;
    const float* x    = (const float*)d_in[0];
    const float* td0  = (const float*)d_in[1];
    const float* td1  = (const float*)d_in[2];
    const float* hx   = (const float*)d_in[3];
    const float* cx   = (const float*)d_in[4];
    const float* w_ih = (const float*)d_in[5];
    const float* w_hh = (const float*)d_in[6];
    const float* w_pi = (const float*)d_in[7];
    const float* w_pf = (const float*)d_in[8];
    const float* w_po = (const float*)d_in[9];
    const float* b_ih = (const float*)d_in[10];
    const float* b_hh = (const float*)d_in[11];
    const float* aS   = (const float*)d_in[12];
    const float* bS   = (const float*)d_in[13];
    (void)cx;

    float* out = (float*)d_out;
    float* hy  = out;                        // [B, OUT]
    float* cy  = out + (size_t)BSZ * OUTF;   // [B, OUT]

    // symbol addresses for fp16 buffers
    void *p_xh, *p_hxh, *p_cxh, *p_wih, *p_whh, *p_wp, *p_wpo;
    cudaGetSymbolAddress(&p_xh,  g_xh);
    cudaGetSymbolAddress(&p_hxh, g_hxh);
    cudaGetSymbolAddress(&p_cxh, g_cxh);
    cudaGetSymbolAddress(&p_wih, g_wih);
    cudaGetSymbolAddress(&p_whh, g_whh);
    cudaGetSymbolAddress(&p_wp,  g_wp);
    cudaGetSymbolAddress(&p_wpo, g_wpo);

    const int actN8 = BSZ * KDIM / 8;        // activations
    const int wBigN8 = NG * KDIM / 8;        // w_ih / w_hh
    const int wSmN8 = OUTF * KDIM / 8;       // peephole / output weights

    F2HSeg s0 = {(const float4*)x,    (uint4*)p_xh,  actN8};
    F2HSeg s1 = {(const float4*)hx,   (uint4*)p_hxh, actN8};
    F2HSeg s2 = {(const float4*)cx,   (uint4*)p_cxh, actN8};
    F2HSeg s3 = {(const float4*)w_ih, (uint4*)p_wih, wBigN8};
    F2HSeg s4 = {(const float4*)w_hh, (uint4*)p_whh, wBigN8};
    F2HSeg s5 = {(const float4*)w_pi, (uint4*)p_wp,  wSmN8};
    F2HSeg s6 = {(const float4*)w_pf,
                 (uint4*)((char*)p_wp + (size_t)OUTF * KDIM * sizeof(__half)), wSmN8};
    F2HSeg s7 = {(const float4*)w_po, (uint4*)p_wpo, wSmN8};

    f2h_all<<<dim3(1024, 8), 256>>>(s0, s1, s2, s3, s4, s5, s6, s7);

    cudaFuncSetAttribute(gemm_gates, cudaFuncAttributeMaxDynamicSharedMemorySize, SMEM_TOTAL);
    cudaFuncSetAttribute(gemm_out,   cudaFuncAttributeMaxDynamicSharedMemorySize, SMEM_TOTAL);

    gemm_gates<<<dim3(BSZ / 128, NG / 128), 256, SMEM_TOTAL>>>(b_ih, b_hh);

    cell_kernel<<<(BSZ * OUTF / 8 + 255) / 256, 256>>>(td0, td1, aS, bS, cy);

    gemm_out<<<dim3(BSZ / 128, OUTF / 128), 256, SMEM_TOTAL>>>(hy);
}

// round 15
// speedup vs baseline: 1.1860x; 1.0179x over previous
#include <cuda_runtime.h>
#include <cuda_fp16.h>
#include <cstdint>
#include <math.h>

#define BSZ  4096
#define OUTF 2048
#define NG   8192
#define KDIM 2048

// fp16 gate pre-activations scratch [B, 4*OUT]
__device__ __half g_gates[(size_t)BSZ * NG];   // 64 MiB

// fp16 copies (filled by prologue converts / cell kernel)
__device__ __half g_xh [(size_t)BSZ * KDIM];
__device__ __half g_hxh[(size_t)BSZ * KDIM];
__device__ __half g_cxh[(size_t)BSZ * KDIM];
__device__ __half g_cyh[(size_t)BSZ * KDIM];
__device__ __half g_wih[(size_t)NG * KDIM];
__device__ __half g_whh[(size_t)NG * KDIM];
__device__ __half g_wp [(size_t)2 * OUTF * KDIM];   // w_pi rows then w_pf rows
__device__ __half g_wpo[(size_t)OUTF * KDIM];

__device__ __forceinline__ uint32_t smem_u32(const void* p) {
    uint32_t a;
    asm("{ .reg .u64 t; cvta.to.shared.u64 t, %1; cvt.u32.u64 %0, t; }" : "=r"(a) : "l"(p));
    return a;
}

// HW tanh (sm_75+): ~2 ulp, plenty for 1e-3 tolerance
__device__ __forceinline__ float tanh_fast(float x) {
    float r;
    asm("tanh.approx.f32 %0, %1;" : "=f"(r) : "f"(x));
    return r;
}
// sigmoid via tanh identity: one MUFU-class op instead of expf chain
__device__ __forceinline__ float sig_fast(float x) {
    return fmaf(tanh_fast(0.5f * x), 0.5f, 0.5f);
}

__device__ __forceinline__ uint32_t sw128(uint32_t off) {
    return off ^ ((off >> 3) & 0x70);
}

__device__ __forceinline__ void ldsm4(uint32_t addr, uint32_t* r) {
    asm volatile("ldmatrix.sync.aligned.m8n8.x4.shared.b16 {%0,%1,%2,%3}, [%4];"
        : "=r"(r[0]), "=r"(r[1]), "=r"(r[2]), "=r"(r[3]) : "r"(addr));
}

__device__ __forceinline__ void mma16816(float* d, const uint32_t* a, const uint32_t* b) {
    asm volatile(
        "mma.sync.aligned.m16n8k16.row.col.f32.f16.f16.f32 "
        "{%0,%1,%2,%3}, {%4,%5,%6,%7}, {%8,%9}, {%0,%1,%2,%3};"
        : "+f"(d[0]), "+f"(d[1]), "+f"(d[2]), "+f"(d[3])
        : "r"(a[0]), "r"(a[1]), "r"(a[2]), "r"(a[3]), "r"(b[0]), "r"(b[1]));
}

__device__ __forceinline__ void cpa16(uint32_t dst, const void* src) {
    asm volatile("cp.async.cg.shared.global [%0], [%1], 16;" :: "r"(dst), "l"(src));
}
#define CP_COMMIT() asm volatile("cp.async.commit_group;" ::: "memory")
#define CP_WAIT1()  asm volatile("cp.async.wait_group 1;"  ::: "memory")
#define CP_WAIT0()  asm volatile("cp.async.wait_group 0;"  ::: "memory")

// ---------------- SMEM layout ----------------
// header 1024B: bias[128] floats (gates kernel only)
// stage (32KB): A 16KB (128 rows x 128B) | B 16KB (128 rows x 128B), fp16, SW128
// 3 stages; ~97KB/CTA -> 2 CTAs per SM.
#define HDR       1024
#define T_A       0
#define T_B       16384
#define STAGE_SZ  32768
#define NSTAGE    3
#define SMEM_TOTAL (HDR + NSTAGE * STAGE_SZ)   // 99328

// async-load one K=64 chunk: A 128 rows, B 128 rows (fp16 global, row stride KDIM)
__device__ __forceinline__ void load_chunk(const __half* __restrict__ Ab,
                                           const __half* __restrict__ Bb,
                                           uint32_t stage, int tid) {
    #pragma unroll
    for (int it = 0; it < 4; ++it) {
        int idx = tid + it * 256;
        int r = idx >> 3, c16 = idx & 7;
        cpa16(stage + T_A + sw128((uint32_t)(r * 128 + c16 * 16)),
              Ab + (size_t)r * KDIM + c16 * 8);
    }
    #pragma unroll
    for (int it = 0; it < 4; ++it) {
        int idx = tid + it * 256;
        int r = idx >> 3, c16 = idx & 7;
        cpa16(stage + T_B + sw128((uint32_t)(r * 128 + c16 * 16)),
              Bb + (size_t)r * KDIM + c16 * 8);
    }
}

// Compute one K=64 chunk (4 k16 steps): warp tile 64(M) x 32(N).
__device__ __forceinline__ void compute_chunk(uint32_t stage_addr, int wm, int wn,
                                              int lane, float (&acc)[4][4][4]) {
    const uint32_t a_base = stage_addr + T_A;
    const uint32_t b_base = stage_addr + T_B;
    const int a_m = lane % 16;
    const int a_k = (lane / 16) * 8;
    const int b_n = (lane / 16) * 8 + (lane % 8);
    const int b_k = ((lane / 8) % 2) * 8;

    #pragma unroll
    for (int kk = 0; kk < 4; ++kk) {
        uint32_t Ah[4][4], Bh[2][4];
        #pragma unroll
        for (int mt = 0; mt < 4; ++mt) {
            uint32_t off = sw128((uint32_t)((wm + mt * 16 + a_m) * 128 + kk * 32 + a_k * 2));
            ldsm4(a_base + off, Ah[mt]);
        }
        #pragma unroll
        for (int nt = 0; nt < 2; ++nt) {
            uint32_t off = sw128((uint32_t)((wn + nt * 16 + b_n) * 128 + kk * 32 + b_k * 2));
            ldsm4(b_base + off, Bh[nt]);
        }
        #pragma unroll
        for (int mt = 0; mt < 4; ++mt)
            #pragma unroll
            for (int n8 = 0; n8 < 4; ++n8)
                mma16816(acc[mt][n8], Ah[mt], &Bh[n8 >> 1][(n8 & 1) * 2]);
    }
}

// ---------------------------------------------------------------------------
// Merged fp32 -> fp16 converter: 8 floats per thread, single 16B store.
// ---------------------------------------------------------------------------
struct F2HSeg { const float4* src; uint4* dst; int n8; };

__global__ __launch_bounds__(256)
void f2h_all(F2HSeg s0, F2HSeg s1, F2HSeg s2, F2HSeg s3,
             F2HSeg s4, F2HSeg s5, F2HSeg s6, F2HSeg s7) {
    F2HSeg s;
    switch (blockIdx.y) {
        case 0: s = s0; break; case 1: s = s1; break;
        case 2: s = s2; break; case 3: s = s3; break;
        case 4: s = s4; break; case 5: s = s5; break;
        case 6: s = s6; break; default: s = s7; break;
    }
    const int stride = gridDim.x * blockDim.x;
    for (int i = blockIdx.x * blockDim.x + threadIdx.x; i < s.n8; i += stride) {
        float4 v0 = s.src[i * 2];
        float4 v1 = s.src[i * 2 + 1];
        __half2 h0 = __floats2half2_rn(v0.x, v0.y);
        __half2 h1 = __floats2half2_rn(v0.z, v0.w);
        __half2 h2 = __floats2half2_rn(v1.x, v1.y);
        __half2 h3 = __floats2half2_rn(v1.z, v1.w);
        uint4 o;
        o.x = *reinterpret_cast<uint32_t*>(&h0);
        o.y = *reinterpret_cast<uint32_t*>(&h1);
        o.z = *reinterpret_cast<uint32_t*>(&h2);
        o.w = *reinterpret_cast<uint32_t*>(&h3);
        s.dst[i] = o;
    }
}

// ---------------------------------------------------------------------------
// GEMM1: gates[B, 8192] = x@w_ih^T + hx@w_hh^T (+ cx@w_p{i,f}^T) + biases
// grid = (32 m-tiles, 64 n-tiles), block = 256. CTA tile 128x128, 2 CTAs/SM.
// ---------------------------------------------------------------------------
__global__ __launch_bounds__(256, 2)
void gemm_gates(const float* __restrict__ b_ih, const float* __restrict__ b_hh)
{
    extern __shared__ char sm[];
    const int tid  = threadIdx.x;
    const int wid  = tid >> 5;
    const int lane = tid & 31;
    const int m0   = blockIdx.x * 128;
    const int n0   = blockIdx.y * 128;
    const int wm   = (wid & 1) * 64;
    const int wn   = (wid >> 1) * 32;

    float* bsum = reinterpret_cast<float*>(sm);
    if (tid < 128) bsum[tid] = b_ih[n0 + tid] + b_hh[n0 + tid];

    const uint32_t smb = smem_u32(sm);
    const int nseg = (n0 < 2 * OUTF) ? 3 : 2;
    const __half* segA[3];
    const __half* segB[3];
    segA[0] = g_xh  + (size_t)m0 * KDIM; segB[0] = g_wih + (size_t)n0 * KDIM;
    segA[1] = g_hxh + (size_t)m0 * KDIM; segB[1] = g_whh + (size_t)n0 * KDIM;
    segA[2] = g_cxh + (size_t)m0 * KDIM; segB[2] = g_wp  + (size_t)n0 * KDIM;

    float acc[4][4][4];
    #pragma unroll
    for (int i = 0; i < 4; ++i)
        #pragma unroll
        for (int j = 0; j < 4; ++j)
            #pragma unroll
            for (int k = 0; k < 4; ++k) acc[i][j][k] = 0.f;

    const int nch = nseg * 32;

    auto issue = [&](int c) {
        const int seg = c >> 5;
        const int kc  = (c & 31) << 6;
        load_chunk(segA[seg] + kc, segB[seg] + kc,
                   smb + HDR + (uint32_t)(c % NSTAGE) * STAGE_SZ, tid);
        CP_COMMIT();
    };

    issue(0);
    issue(1);

    for (int c = 0; c < nch; ++c) {
        if (c + 1 < nch) { CP_WAIT1(); } else { CP_WAIT0(); }
        __syncthreads();
        if (c + 2 < nch) issue(c + 2);
        compute_chunk(smb + HDR + (uint32_t)(c % NSTAGE) * STAGE_SZ, wm, wn, lane, acc);
    }

    // epilogue: bias + store fp16 preacts
    #pragma unroll
    for (int mt = 0; mt < 4; ++mt) {
        #pragma unroll
        for (int n8 = 0; n8 < 4; ++n8) {
            int lcol = wn + n8 * 8 + (lane % 4) * 2;
            float bx0 = bsum[lcol], bx1 = bsum[lcol + 1];
            int r0 = m0 + wm + mt * 16 + lane / 4;
            __half* g0 = g_gates + (size_t)r0 * NG + n0 + lcol;
            __half* g1 = g_gates + (size_t)(r0 + 8) * NG + n0 + lcol;
            *reinterpret_cast<__half2*>(g0) =
                __floats2half2_rn(acc[mt][n8][0] + bx0, acc[mt][n8][1] + bx1);
            *reinterpret_cast<__half2*>(g1) =
                __floats2half2_rn(acc[mt][n8][2] + bx0, acc[mt][n8][3] + bx1);
        }
    }
}

// ---------------------------------------------------------------------------
// Cell update: cy = a*exp(-b*td0)*sig(f)*cx + a*exp(-b*td1)*sig(i)*tanh(g)
// Reads fp16 preacts + fp16 cx; writes cy fp32 (d_out) and cy fp16 (g_cyh).
// ---------------------------------------------------------------------------
__device__ __forceinline__ void unpack8(uint4 u, float* o) {
    float2 t;
    t = __half22float2(*reinterpret_cast<__half2*>(&u.x)); o[0] = t.x; o[1] = t.y;
    t = __half22float2(*reinterpret_cast<__half2*>(&u.y)); o[2] = t.x; o[3] = t.y;
    t = __half22float2(*reinterpret_cast<__half2*>(&u.z)); o[4] = t.x; o[5] = t.y;
    t = __half22float2(*reinterpret_cast<__half2*>(&u.w)); o[6] = t.x; o[7] = t.y;
}

__global__ __launch_bounds__(256)
void cell_kernel(const float* __restrict__ td0, const float* __restrict__ td1,
                 const float* __restrict__ aS,  const float* __restrict__ bS,
                 float* __restrict__ cy_out)
{
    size_t idx = (size_t)blockIdx.x * blockDim.x + threadIdx.x;
    const size_t total = (size_t)BSZ * OUTF / 8;
    if (idx >= total) return;
    int row = (int)(idx / (OUTF / 8));
    int c   = (int)(idx % (OUTF / 8)) * 8;

    float a = aS[0], b = bS[0];
    float forc = a * __expf(-b * td0[row]);
    float inc  = a * __expf(-b * td1[row]);

    const __half* grow = g_gates + (size_t)row * NG;
    float iv[8], fv[8], gv[8], cxv[8];
    unpack8(*reinterpret_cast<const uint4*>(grow + c),            iv);
    unpack8(*reinterpret_cast<const uint4*>(grow + OUTF + c),     fv);
    unpack8(*reinterpret_cast<const uint4*>(grow + 2 * OUTF + c), gv);
    unpack8(*reinterpret_cast<const uint4*>(g_cxh + (size_t)row * OUTF + c), cxv);

    float cyv[8];
    #pragma unroll
    for (int j = 0; j < 8; ++j)
        cyv[j] = forc * sig_fast(fv[j]) * cxv[j] + inc * sig_fast(iv[j]) * tanh_fast(gv[j]);

    float* cyp = cy_out + (size_t)row * OUTF + c;
    *reinterpret_cast<float4*>(cyp)     = make_float4(cyv[0], cyv[1], cyv[2], cyv[3]);
    *reinterpret_cast<float4*>(cyp + 4) = make_float4(cyv[4], cyv[5], cyv[6], cyv[7]);

    __half2 h0 = __floats2half2_rn(cyv[0], cyv[1]);
    __half2 h1 = __floats2half2_rn(cyv[2], cyv[3]);
    __half2 h2 = __floats2half2_rn(cyv[4], cyv[5]);
    __half2 h3 = __floats2half2_rn(cyv[6], cyv[7]);
    uint4 packed;
    packed.x = *reinterpret_cast<uint32_t*>(&h0);
    packed.y = *reinterpret_cast<uint32_t*>(&h1);
    packed.z = *reinterpret_cast<uint32_t*>(&h2);
    packed.w = *reinterpret_cast<uint32_t*>(&h3);
    *reinterpret_cast<uint4*>(g_cyh + (size_t)row * OUTF + c) = packed;
}

// ---------------------------------------------------------------------------
// GEMM3: O = cy @ w_po^T ; hy = sigmoid(o_preact + O) * tanh(cy)
// grid = (32 m-tiles, 16 n-tiles), block = 256. CTA tile 128x128, 2 CTAs/SM.
// ---------------------------------------------------------------------------
__global__ __launch_bounds__(256, 2)
void gemm_out(float* __restrict__ hy)
{
    extern __shared__ char sm[];
    const int tid  = threadIdx.x;
    const int wid  = tid >> 5;
    const int lane = tid & 31;
    const int m0   = blockIdx.x * 128;
    const int n0   = blockIdx.y * 128;
    const int wm   = (wid & 1) * 64;
    const int wn   = (wid >> 1) * 32;

    const uint32_t smb = smem_u32(sm);
    const __half* Ab = g_cyh + (size_t)m0 * KDIM;
    const __half* Bb = g_wpo + (size_t)n0 * KDIM;

    float acc[4][4][4];
    #pragma unroll
    for (int i = 0; i < 4; ++i)
        #pragma unroll
        for (int j = 0; j < 4; ++j)
            #pragma unroll
            for (int k = 0; k < 4; ++k) acc[i][j][k] = 0.f;

    const int nch = 32;

    auto issue = [&](int c) {
        const int kc = c << 6;
        load_chunk(Ab + kc, Bb + kc,
                   smb + HDR + (uint32_t)(c % NSTAGE) * STAGE_SZ, tid);
        CP_COMMIT();
    };

    issue(0);
    issue(1);

    for (int c = 0; c < nch; ++c) {
        if (c + 1 < nch) { CP_WAIT1(); } else { CP_WAIT0(); }
        __syncthreads();
        if (c + 2 < nch) issue(c + 2);
        compute_chunk(smb + HDR + (uint32_t)(c % NSTAGE) * STAGE_SZ, wm, wn, lane, acc);
    }

    // fused epilogue (o preacts fp16, cy fp16; HW tanh)
    #pragma unroll
    for (int mt = 0; mt < 4; ++mt) {
        #pragma unroll
        for (int n8 = 0; n8 < 4; ++n8) {
            int col = n0 + wn + n8 * 8 + (lane % 4) * 2;
            #pragma unroll
            for (int half = 0; half < 2; ++half) {
                int row = m0 + wm + mt * 16 + lane / 4 + half * 8;
                const __half* gorow = g_gates + (size_t)row * NG + 3 * OUTF + col;
                const __half* cyrow = g_cyh + (size_t)row * OUTF + col;
                float*        hyrow = hy + (size_t)row * OUTF + col;
                float2 go  = __half22float2(*reinterpret_cast<const __half2*>(gorow));
                float2 cyv = __half22float2(*reinterpret_cast<const __half2*>(cyrow));
                float2 r;
                r.x = sig_fast(go.x + acc[mt][n8][half * 2 + 0]) * tanh_fast(cyv.x);
                r.y = sig_fast(go.y + acc[mt][n8][half * 2 + 1]) * tanh_fast(cyv.y);
                *reinterpret_cast<float2*>(hyrow) = r;
            }
        }
    }
}

// ---------------------------------------------------------------------------
extern "C" void kernel_launch(void* const* d_in, const int* in_sizes, int n_in,
                              void* d_out, int out_size)
{
    (void)in_sizes; (void)n_in; (void)out_size;
    const float* x    = (const float*)d_in[0];
    const float* td0  = (const float*)d_in[1];
    const float* td1  = (const float*)d_in[2];
    const float* hx   = (const float*)d_in[3];
    const float* cx   = (const float*)d_in[4];
    const float* w_ih = (const float*)d_in[5];
    const float* w_hh = (const float*)d_in[6];
    const float* w_pi = (const float*)d_in[7];
    const float* w_pf = (const float*)d_in[8];
    const float* w_po = (const float*)d_in[9];
    const float* b_ih = (const float*)d_in[10];
    const float* b_hh = (const float*)d_in[11];
    const float* aS   = (const float*)d_in[12];
    const float* bS   = (const float*)d_in[13];

    float* out = (float*)d_out;
    float* hy  = out;                        // [B, OUT]
    float* cy  = out + (size_t)BSZ * OUTF;   // [B, OUT]

    // symbol addresses for fp16 buffers
    void *p_xh, *p_hxh, *p_cxh, *p_wih, *p_whh, *p_wp, *p_wpo;
    cudaGetSymbolAddress(&p_xh,  g_xh);
    cudaGetSymbolAddress(&p_hxh, g_hxh);
    cudaGetSymbolAddress(&p_cxh, g_cxh);
    cudaGetSymbolAddress(&p_wih, g_wih);
    cudaGetSymbolAddress(&p_whh, g_whh);
    cudaGetSymbolAddress(&p_wp,  g_wp);
    cudaGetSymbolAddress(&p_wpo, g_wpo);

    const int actN8 = BSZ * KDIM / 8;        // activations
    const int wBigN8 = NG * KDIM / 8;        // w_ih / w_hh
    const int wSmN8 = OUTF * KDIM / 8;       // peephole / output weights

    F2HSeg s0 = {(const float4*)x,    (uint4*)p_xh,  actN8};
    F2HSeg s1 = {(const float4*)hx,   (uint4*)p_hxh, actN8};
    F2HSeg s2 = {(const float4*)cx,   (uint4*)p_cxh, actN8};
    F2HSeg s3 = {(const float4*)w_ih, (uint4*)p_wih, wBigN8};
    F2HSeg s4 = {(const float4*)w_hh, (uint4*)p_whh, wBigN8};
    F2HSeg s5 = {(const float4*)w_pi, (uint4*)p_wp,  wSmN8};
    F2HSeg s6 = {(const float4*)w_pf,
                 (uint4*)((char*)p_wp + (size_t)OUTF * KDIM * sizeof(__half)), wSmN8};
    F2HSeg s7 = {(const float4*)w_po, (uint4*)p_wpo, wSmN8};

    f2h_all<<<dim3(1024, 8), 256>>>(s0, s1, s2, s3, s4, s5, s6, s7);

    cudaFuncSetAttribute(gemm_gates, cudaFuncAttributeMaxDynamicSharedMemorySize, SMEM_TOTAL);
    cudaFuncSetAttribute(gemm_out,   cudaFuncAttributeMaxDynamicSharedMemorySize, SMEM_TOTAL);

    gemm_gates<<<dim3(BSZ / 128, NG / 128), 256, SMEM_TOTAL>>>(b_ih, b_hh);

    cell_kernel<<<(BSZ * OUTF / 8 + 255) / 256, 256>>>(td0, td1, aS, bS, cy);

    gemm_out<<<dim3(BSZ / 128, OUTF / 128), 256, SMEM_TOTAL>>>(hy);
}